// round 1
// baseline (speedup 1.0000x reference)
#include <cuda_runtime.h>
#include <cstdint>

// Problem constants (fixed instance)
#define N1c 2000     // landmarks
#define N2c 2000     // targets
#define NNc 4000     // total nodes
#define NPADc 4096   // padded node count for tile loads
#define Dc 63        // feature dim
#define Ec 64        // embedding dim
#define Hc 8         // heads
#define KNNc 5

// -------- device scratch (no allocations allowed) --------
__device__ float g_A[Hc * Ec * NPADc];   // [h][e][n]  normalized a-vectors
__device__ float g_B[Hc * Ec * NPADc];   // [h][e][n]  normalized b-vectors
__device__ float g_sq[N1c];              // row squared norms of lm_X

// =====================================================================
// teacher adjacency fill: top-left 0 (KNN scattered later), off-diag
// blocks 1, bottom-right 0.
// =====================================================================
__global__ void fill_teacher_kernel(float* __restrict__ t) {
    int j = (blockIdx.x * 256 + threadIdx.x) * 4;
    int i = blockIdx.y;
    if (j < NNc) {
        float v = ((i < N1c) != (j < N1c)) ? 1.0f : 0.0f;
        float4 vv = make_float4(v, v, v, v);
        *(float4*)&t[(size_t)i * NNc + j] = vv;
    }
}

// =====================================================================
// squared norms of landmark rows
// =====================================================================
__global__ void sq_kernel(const float* __restrict__ lm_X) {
    int n = blockIdx.x * blockDim.x + threadIdx.x;
    if (n < N1c) {
        float s = 0.f;
        #pragma unroll
        for (int k = 0; k < Dc; k++) {
            float x = lm_X[n * Dc + k];
            s = fmaf(x, x, s);
        }
        g_sq[n] = s;
    }
}

// =====================================================================
// embedding + per-head normalized vectors
// one block (64 threads) per node; pad nodes write zeros.
// =====================================================================
__global__ void embed_kernel(const float* __restrict__ lm_X,
                             const float* __restrict__ tg_X,
                             const float* __restrict__ lm_delay,
                             const float* __restrict__ tg_delay,
                             const float* __restrict__ W_emb,
                             const float* __restrict__ b_emb,
                             const float* __restrict__ w1,
                             const float* __restrict__ w2) {
    __shared__ float feat[Ec];
    __shared__ float Wsh[Ec * 65];   // padded to kill bank conflicts
    __shared__ float red[2];

    const int n = blockIdx.x;
    const int j = threadIdx.x;

    if (n >= NNc) {
        // zero padding region
        for (int h = 0; h < Hc; h++) {
            g_A[(h * Ec + j) * NPADc + n] = 0.f;
            g_B[(h * Ec + j) * NPADc + n] = 0.f;
        }
        return;
    }

    if (j < Dc) feat[j] = (n < N1c) ? lm_X[n * Dc + j] : tg_X[(n - N1c) * Dc + j];
    else        feat[j] = (n < N1c) ? lm_delay[n]      : tg_delay[n - N1c];

    for (int idx = j; idx < Ec * Ec; idx += Ec)
        Wsh[(idx >> 6) * 65 + (idx & 63)] = W_emb[idx];
    __syncthreads();

    float ej = b_emb[j];
    #pragma unroll
    for (int k = 0; k < Ec; k++)
        ej = fmaf(Wsh[j * 65 + k], feat[k], ej);

    #pragma unroll 1
    for (int h = 0; h < Hc; h++) {
        float a = ej * w1[j * Hc + h];
        float b = ej * w2[j * Hc + h];

        // block sum of a*a over the 64 threads
        float va = a * a;
        #pragma unroll
        for (int o = 16; o > 0; o >>= 1) va += __shfl_xor_sync(0xffffffffu, va, o);
        if ((j & 31) == 0) red[j >> 5] = va;
        __syncthreads();
        float sa = red[0] + red[1];
        __syncthreads();

        float vb = b * b;
        #pragma unroll
        for (int o = 16; o > 0; o >>= 1) vb += __shfl_xor_sync(0xffffffffu, vb, o);
        if ((j & 31) == 0) red[j >> 5] = vb;
        __syncthreads();
        float sb = red[0] + red[1];
        __syncthreads();

        g_A[(h * Ec + j) * NPADc + n] = a * rsqrtf(sa);
        g_B[(h * Ec + j) * NPADc + n] = b * rsqrtf(sb);
    }
}

// =====================================================================
// KNN (k=5) over landmarks: y_pred + scatter 1s into teacher lm block.
// one block (256 threads) per landmark row.
// =====================================================================
__global__ void knn_kernel(const float* __restrict__ lm_X,
                           const float* __restrict__ lm_Y,
                           float* __restrict__ y_pred,
                           float* __restrict__ teacher) {
    __shared__ float Xn[Dc];
    __shared__ unsigned long long sred[256];

    const int n = blockIdx.x;
    const int tid = threadIdx.x;

    if (tid < Dc) Xn[tid] = lm_X[n * Dc + tid];
    __syncthreads();

    const float sqn = g_sq[n];
    const float INF = __int_as_float(0x7f800000);

    float bd[KNNc];
    int   bi[KNNc];
    #pragma unroll
    for (int t = 0; t < KNNc; t++) { bd[t] = INF; bi[t] = 0; }

    for (int m = tid; m < N1c; m += 256) {
        if (m == n) continue;
        float dot = 0.f;
        #pragma unroll
        for (int k = 0; k < Dc; k++)
            dot = fmaf(lm_X[m * Dc + k], Xn[k], dot);
        float d2 = sqn + g_sq[m] - 2.f * dot;
        d2 = fmaxf(d2, 0.f);
        if (d2 < bd[KNNc - 1]) {
            bd[KNNc - 1] = d2; bi[KNNc - 1] = m;
            #pragma unroll
            for (int t = KNNc - 1; t > 0; t--) {
                if (bd[t] < bd[t - 1]) {
                    float td = bd[t]; bd[t] = bd[t - 1]; bd[t - 1] = td;
                    int   ti = bi[t]; bi[t] = bi[t - 1]; bi[t - 1] = ti;
                }
            }
        }
    }

    float y0 = 0.f, y1 = 0.f;
    #pragma unroll 1
    for (int r = 0; r < KNNc; r++) {
        unsigned long long key =
            (((unsigned long long)__float_as_uint(bd[0])) << 32) | (unsigned)bi[0];
        sred[tid] = key;
        __syncthreads();
        #pragma unroll
        for (int s = 128; s > 0; s >>= 1) {
            if (tid < s) {
                unsigned long long o = sred[tid + s];
                if (o < sred[tid]) sred[tid] = o;
            }
            __syncthreads();
        }
        unsigned long long win = sred[0];
        __syncthreads();
        int wm = (int)(win & 0xffffffffull);
        if (key == win) {
            #pragma unroll
            for (int t = 0; t < KNNc - 1; t++) { bd[t] = bd[t + 1]; bi[t] = bi[t + 1]; }
            bd[KNNc - 1] = INF; bi[KNNc - 1] = 0;
        }
        if (tid == 0) {
            teacher[(size_t)n * NNc + wm] = 1.0f;
            y0 += lm_Y[wm * 2 + 0];
            y1 += lm_Y[wm * 2 + 1];
        }
    }
    if (tid == 0) {
        y_pred[n * 2 + 0] = y0 * 0.2f;
        y_pred[n * 2 + 1] = y1 * 0.2f;
    }
}

// =====================================================================
// main adjacency kernel: 128x64 tile, 8x4 per-thread tile, BK=32.
// heads processed sequentially; sigmoid via degree-9 odd polynomial
// (valid since |sim| <= 1), accumulated into head-mean.
// =====================================================================
__device__ __forceinline__ float sigmoid_poly(float x) {
    // sigma(x) = 0.5 + x*(c1 + u*(c3 + u*(c5 + u*(c7 + u*c9)))), u = x^2
    float u = x * x;
    float p = fmaf(u, 2.1356922e-5f, -2.1081349e-4f);
    p = fmaf(u, p, 2.0833333e-3f);
    p = fmaf(u, p, -2.0833334e-2f);
    p = fmaf(u, p, 0.25f);
    return fmaf(x, p, 0.5f);
}

__global__ void __launch_bounds__(256, 2) adj_kernel(float* __restrict__ adj) {
    __shared__ float As[32][128];
    __shared__ float Bs[32][64];

    const int tid = threadIdx.x;
    const int tx = tid >> 4;   // 0..15  (n dim, 8 rows each)
    const int ty = tid & 15;   // 0..15  (m dim, 4 cols each)
    const int n0 = blockIdx.y * 128;
    const int m0 = blockIdx.x * 64;

    float acc[8][4];
    #pragma unroll
    for (int i = 0; i < 8; i++)
        #pragma unroll
        for (int j = 0; j < 4; j++) acc[i][j] = 0.f;

    #pragma unroll 1
    for (int h = 0; h < Hc; h++) {
        float sim[8][4];
        #pragma unroll
        for (int i = 0; i < 8; i++)
            #pragma unroll
            for (int j = 0; j < 4; j++) sim[i][j] = 0.f;

        #pragma unroll 1
        for (int kk = 0; kk < 2; kk++) {
            __syncthreads();
            const float* Ag = g_A + (size_t)(h * Ec + kk * 32) * NPADc + n0;
            const float* Bg = g_B + (size_t)(h * Ec + kk * 32) * NPADc + m0;
            {
                int r = tid >> 5, c = (tid & 31) * 4;
                #pragma unroll
                for (int rr = 0; rr < 4; rr++)
                    *(float4*)&As[r + rr * 8][c] =
                        *(const float4*)&Ag[(size_t)(r + rr * 8) * NPADc + c];
            }
            {
                int r = tid >> 4, c = (tid & 15) * 4;
                #pragma unroll
                for (int rr = 0; rr < 2; rr++)
                    *(float4*)&Bs[r + rr * 16][c] =
                        *(const float4*)&Bg[(size_t)(r + rr * 16) * NPADc + c];
            }
            __syncthreads();

            #pragma unroll 8
            for (int e = 0; e < 32; e++) {
                float a[8], b[4];
                *(float4*)&a[0] = *(float4*)&As[e][tx * 8];
                *(float4*)&a[4] = *(float4*)&As[e][tx * 8 + 4];
                *(float4*)&b[0] = *(float4*)&Bs[e][ty * 4];
                #pragma unroll
                for (int i = 0; i < 8; i++)
                    #pragma unroll
                    for (int j = 0; j < 4; j++)
                        sim[i][j] = fmaf(a[i], b[j], sim[i][j]);
            }
        }

        #pragma unroll
        for (int i = 0; i < 8; i++)
            #pragma unroll
            for (int j = 0; j < 4; j++)
                acc[i][j] += sigmoid_poly(sim[i][j]);
    }

    const int gm = m0 + ty * 4;
    #pragma unroll
    for (int i = 0; i < 8; i++) {
        int gn = n0 + tx * 8 + i;
        if (gn < NNc) {
            if (gm + 3 < NNc) {
                float4 v = make_float4(acc[i][0] * 0.125f, acc[i][1] * 0.125f,
                                       acc[i][2] * 0.125f, acc[i][3] * 0.125f);
                *(float4*)&adj[(size_t)gn * NNc + gm] = v;
            } else {
                #pragma unroll
                for (int j = 0; j < 4; j++)
                    if (gm + j < NNc)
                        adj[(size_t)gn * NNc + gm + j] = acc[i][j] * 0.125f;
            }
        }
    }
}

// =====================================================================
// launch
// =====================================================================
extern "C" void kernel_launch(void* const* d_in, const int* in_sizes, int n_in,
                              void* d_out, int out_size) {
    (void)in_sizes; (void)n_in; (void)out_size;
    const float* lm_X     = (const float*)d_in[0];
    const float* lm_Y     = (const float*)d_in[1];
    const float* tg_X     = (const float*)d_in[2];
    // d_in[3] = tg_Y (unused by reference)
    const float* lm_delay = (const float*)d_in[4];
    const float* tg_delay = (const float*)d_in[5];
    const float* W_emb    = (const float*)d_in[6];
    const float* b_emb    = (const float*)d_in[7];
    const float* w1       = (const float*)d_in[8];
    const float* w2       = (const float*)d_in[9];

    float* out     = (float*)d_out;
    float* y_pred  = out;                       // [2000, 2]
    float* adj     = out + 4000;                // [4000, 4000]
    float* teacher = adj + (size_t)NNc * NNc;   // [4000, 4000]

    fill_teacher_kernel<<<dim3(4, NNc), 256>>>(teacher);
    sq_kernel<<<8, 256>>>(lm_X);
    embed_kernel<<<NPADc, 64>>>(lm_X, tg_X, lm_delay, tg_delay,
                                W_emb, b_emb, w1, w2);
    knn_kernel<<<N1c, 256>>>(lm_X, lm_Y, y_pred, teacher);
    adj_kernel<<<dim3(63, 32), 256>>>(adj);
}

// round 3
// speedup vs baseline: 3.7765x; 3.7765x over previous
#include <cuda_runtime.h>
#include <cuda_bf16.h>
#include <cstdint>

// Problem constants (fixed instance)
#define N1c 2000     // landmarks
#define NNc 4000     // total nodes
#define NPADc 4096   // padded node count
#define Dc 63        // feature dim
#define Ec 64        // embedding dim
#define Hc 8         // heads
#define KNNc 5
#define MPADc 2048   // padded col count for d2 matrix

// -------- device scratch (no allocations allowed) --------
__device__ __nv_bfloat16 g_Abf[(size_t)Hc * NPADc * Ec];  // [h][n][e] normalized a (bf16)
__device__ __nv_bfloat16 g_Bbf[(size_t)Hc * NPADc * Ec];  // [h][n][e] normalized b (bf16)
__device__ float g_sq[N1c];                               // row squared norms of lm_X
__device__ float g_XT[Ec * MPADc];                        // lm_X transposed [64][2048]
__device__ float g_d2[(size_t)N1c * MPADc];               // pairwise squared distances

__device__ __forceinline__ uint32_t smem_u32(const void* p) {
    uint32_t a;
    asm("{ .reg .u64 t; cvta.to.shared.u64 t, %1; cvt.u32.u64 %0, t; }"
        : "=r"(a) : "l"(p));
    return a;
}

// =====================================================================
// teacher adjacency fill
// =====================================================================
__global__ void fill_teacher_kernel(float* __restrict__ t) {
    int j = (blockIdx.x * 256 + threadIdx.x) * 4;
    int i = blockIdx.y;
    if (j < NNc) {
        float v = ((i < N1c) != (j < N1c)) ? 1.0f : 0.0f;
        *(float4*)&t[(size_t)i * NNc + j] = make_float4(v, v, v, v);
    }
}

// =====================================================================
// squared norms of landmark rows
// =====================================================================
__global__ void sq_kernel(const float* __restrict__ lm_X) {
    int n = blockIdx.x * blockDim.x + threadIdx.x;
    if (n < N1c) {
        float s = 0.f;
        #pragma unroll
        for (int k = 0; k < Dc; k++) {
            float x = lm_X[n * Dc + k];
            s = fmaf(x, x, s);
        }
        g_sq[n] = s;
    }
}

// =====================================================================
// transpose lm_X -> g_XT [64][2048] (row 63 and n>=2000 zero)
// =====================================================================
__global__ void xt_kernel(const float* __restrict__ lm_X) {
    int idx = blockIdx.x * 256 + threadIdx.x;
    if (idx < Ec * MPADc) {
        int k = idx / MPADc;
        int n = idx % MPADc;
        g_XT[idx] = (k < Dc && n < N1c) ? lm_X[n * Dc + k] : 0.f;
    }
}

// =====================================================================
// embedding + per-head normalized vectors (bf16 output, [h][n][e])
// =====================================================================
__global__ void embed_kernel(const float* __restrict__ lm_X,
                             const float* __restrict__ tg_X,
                             const float* __restrict__ lm_delay,
                             const float* __restrict__ tg_delay,
                             const float* __restrict__ W_emb,
                             const float* __restrict__ b_emb,
                             const float* __restrict__ w1,
                             const float* __restrict__ w2) {
    __shared__ float feat[Ec];
    __shared__ float Wsh[Ec * 65];
    __shared__ float red[2];

    const int n = blockIdx.x;
    const int j = threadIdx.x;

    if (n >= NNc) {
        for (int h = 0; h < Hc; h++) {
            g_Abf[((size_t)h * NPADc + n) * Ec + j] = __float2bfloat16(0.f);
            g_Bbf[((size_t)h * NPADc + n) * Ec + j] = __float2bfloat16(0.f);
        }
        return;
    }

    if (j < Dc) feat[j] = (n < N1c) ? lm_X[n * Dc + j] : tg_X[(n - N1c) * Dc + j];
    else        feat[j] = (n < N1c) ? lm_delay[n]      : tg_delay[n - N1c];

    for (int idx = j; idx < Ec * Ec; idx += Ec)
        Wsh[(idx >> 6) * 65 + (idx & 63)] = W_emb[idx];
    __syncthreads();

    float ej = b_emb[j];
    #pragma unroll
    for (int k = 0; k < Ec; k++)
        ej = fmaf(Wsh[j * 65 + k], feat[k], ej);

    #pragma unroll 1
    for (int h = 0; h < Hc; h++) {
        float a = ej * w1[j * Hc + h];
        float b = ej * w2[j * Hc + h];

        float va = a * a;
        #pragma unroll
        for (int o = 16; o > 0; o >>= 1) va += __shfl_xor_sync(0xffffffffu, va, o);
        if ((j & 31) == 0) red[j >> 5] = va;
        __syncthreads();
        float sa = red[0] + red[1];
        __syncthreads();

        float vb = b * b;
        #pragma unroll
        for (int o = 16; o > 0; o >>= 1) vb += __shfl_xor_sync(0xffffffffu, vb, o);
        if ((j & 31) == 0) red[j >> 5] = vb;
        __syncthreads();
        float sb = red[0] + red[1];
        __syncthreads();

        g_Abf[((size_t)h * NPADc + n) * Ec + j] = __float2bfloat16(a * rsqrtf(sa));
        g_Bbf[((size_t)h * NPADc + n) * Ec + j] = __float2bfloat16(b * rsqrtf(sb));
    }
}

// =====================================================================
// d2 GEMM: d2[n][m] = sq[n] + sq[m] - 2*dot, diag/pad = +inf
// =====================================================================
__global__ void __launch_bounds__(256) d2_kernel() {
    __shared__ float As[Ec][64];
    __shared__ float Bs[Ec][64];

    const int tid = threadIdx.x;
    const int tx = tid >> 4, ty = tid & 15;
    const int n0 = blockIdx.y * 64, m0 = blockIdx.x * 64;

    #pragma unroll
    for (int p = 0; p < 16; p++) {
        int idx = p * 256 + tid;
        int k = idx >> 6, r = idx & 63;
        As[k][r] = g_XT[k * MPADc + n0 + r];
        Bs[k][r] = g_XT[k * MPADc + m0 + r];
    }
    __syncthreads();

    float dot[4][4];
    #pragma unroll
    for (int i = 0; i < 4; i++)
        #pragma unroll
        for (int j = 0; j < 4; j++) dot[i][j] = 0.f;

    #pragma unroll 16
    for (int k = 0; k < Ec; k++) {
        float a[4], b[4];
        #pragma unroll
        for (int i = 0; i < 4; i++) a[i] = As[k][tx * 4 + i];
        #pragma unroll
        for (int j = 0; j < 4; j++) b[j] = Bs[k][ty * 4 + j];
        #pragma unroll
        for (int i = 0; i < 4; i++)
            #pragma unroll
            for (int j = 0; j < 4; j++)
                dot[i][j] = fmaf(a[i], b[j], dot[i][j]);
    }

    const float INF = __int_as_float(0x7f800000);
    #pragma unroll
    for (int i = 0; i < 4; i++) {
        int n = n0 + tx * 4 + i;
        if (n >= N1c) continue;
        float sqn = g_sq[n];
        #pragma unroll
        for (int j = 0; j < 4; j++) {
            int m = m0 + ty * 4 + j;
            float v = INF;
            if (m < N1c && m != n)
                v = fmaxf(sqn + g_sq[m] - 2.f * dot[i][j], 0.f);
            g_d2[(size_t)n * MPADc + m] = v;
        }
    }
}

// =====================================================================
// top-5 per row from d2 matrix; y_pred + teacher scatter
// =====================================================================
__global__ void topk_kernel(const float* __restrict__ lm_Y,
                            float* __restrict__ y_pred,
                            float* __restrict__ teacher) {
    __shared__ unsigned long long sred[256];
    const int n = blockIdx.x;
    const int tid = threadIdx.x;
    const float INF = __int_as_float(0x7f800000);

    float bd[KNNc];
    int   bi[KNNc];
    #pragma unroll
    for (int t = 0; t < KNNc; t++) { bd[t] = INF; bi[t] = 0; }

    #pragma unroll
    for (int it = 0; it < 8; it++) {
        int m = it * 256 + tid;
        float d2 = g_d2[(size_t)n * MPADc + m];
        if (d2 < bd[KNNc - 1]) {
            bd[KNNc - 1] = d2; bi[KNNc - 1] = m;
            #pragma unroll
            for (int t = KNNc - 1; t > 0; t--) {
                if (bd[t] < bd[t - 1]) {
                    float td = bd[t]; bd[t] = bd[t - 1]; bd[t - 1] = td;
                    int   ti = bi[t]; bi[t] = bi[t - 1]; bi[t - 1] = ti;
                }
            }
        }
    }

    float y0 = 0.f, y1 = 0.f;
    #pragma unroll 1
    for (int r = 0; r < KNNc; r++) {
        unsigned long long key =
            (((unsigned long long)__float_as_uint(bd[0])) << 32) | (unsigned)bi[0];
        sred[tid] = key;
        __syncthreads();
        #pragma unroll
        for (int s = 128; s > 0; s >>= 1) {
            if (tid < s) {
                unsigned long long o = sred[tid + s];
                if (o < sred[tid]) sred[tid] = o;
            }
            __syncthreads();
        }
        unsigned long long win = sred[0];
        __syncthreads();
        int wm = (int)(win & 0xffffffffull);
        if (key == win) {
            #pragma unroll
            for (int t = 0; t < KNNc - 1; t++) { bd[t] = bd[t + 1]; bi[t] = bi[t + 1]; }
            bd[KNNc - 1] = INF; bi[KNNc - 1] = 0;
        }
        if (tid == 0) {
            teacher[(size_t)n * NNc + wm] = 1.0f;
            y0 += lm_Y[wm * 2 + 0];
            y1 += lm_Y[wm * 2 + 1];
        }
    }
    if (tid == 0) {
        y_pred[n * 2 + 0] = y0 * 0.2f;
        y_pred[n * 2 + 1] = y1 * 0.2f;
    }
}

// =====================================================================
// sigmoid via degree-9 odd polynomial (|x| <~ 1.01, err ~2e-6)
// =====================================================================
__device__ __forceinline__ float sigmoid_poly(float x) {
    float u = x * x;
    float p = fmaf(u, 2.1356922e-5f, -2.1081349e-4f);
    p = fmaf(u, p, 2.0833333e-3f);
    p = fmaf(u, p, -2.0833334e-2f);
    p = fmaf(u, p, 0.25f);
    return fmaf(x, p, 0.5f);
}

// =====================================================================
// HMMA adjacency kernel: 128x128 tile per CTA, 8 warps (2 x 4),
// each warp 64x32 via mma.sync.m16n8k16 bf16. Heads looped with
// double-buffered smem; XOR-swizzled tiles for conflict-free ldmatrix.
// =====================================================================
#define TILE_BYTES 16384            // 128 rows x 128B
#define BUF_BYTES  (2 * TILE_BYTES) // A + B per stage

__device__ __forceinline__ void ldsm_x4(uint32_t* r, uint32_t addr) {
    asm volatile("ldmatrix.sync.aligned.m8n8.x4.shared.b16 {%0,%1,%2,%3}, [%4];"
                 : "=r"(r[0]), "=r"(r[1]), "=r"(r[2]), "=r"(r[3]) : "r"(addr));
}
__device__ __forceinline__ void ldsm_x2(uint32_t* r, uint32_t addr) {
    asm volatile("ldmatrix.sync.aligned.m8n8.x2.shared.b16 {%0,%1}, [%2];"
                 : "=r"(r[0]), "=r"(r[1]) : "r"(addr));
}
__device__ __forceinline__ void mma_bf16(float* c, const uint32_t* a,
                                         const uint32_t* b) {
    asm volatile(
        "mma.sync.aligned.m16n8k16.row.col.f32.bf16.bf16.f32 "
        "{%0,%1,%2,%3}, {%4,%5,%6,%7}, {%8,%9}, {%0,%1,%2,%3};"
        : "+f"(c[0]), "+f"(c[1]), "+f"(c[2]), "+f"(c[3])
        : "r"(a[0]), "r"(a[1]), "r"(a[2]), "r"(a[3]), "r"(b[0]), "r"(b[1]));
}

__global__ void __launch_bounds__(256, 1) adj_mm_kernel(float* __restrict__ adj) {
    extern __shared__ char dsm[];
    uint32_t dbase = smem_u32(dsm);
    uint32_t abase = (dbase + 1023u) & ~1023u;
    char* sm = dsm + (abase - dbase);

    const int tid = threadIdx.x;
    const int lane = tid & 31;
    const int wid = tid >> 5;
    const int wm = wid & 1;    // 2 warp-rows of 64
    const int wn = wid >> 1;   // 4 warp-cols of 32
    const int n0 = blockIdx.y * 128;
    const int m0 = blockIdx.x * 128;

    // cooperative swizzled tile load: 128 rows x 128B per tile
    auto load_tile = [&](char* dst, const __nv_bfloat16* src) {
        #pragma unroll
        for (int p = 0; p < 4; p++) {
            int row = p * 32 + (tid >> 3);
            int seg = tid & 7;
            uint32_t off = row * 128 + seg * 16;
            uint32_t sw = off ^ ((off >> 3) & 0x70);
            *(uint4*)(dst + sw) =
                *(const uint4*)((const char*)(src + (size_t)row * Ec) + seg * 16);
        }
    };

    // ldmatrix per-thread address components
    const int a_row = wm * 64 + (lane & 7) + ((lane >> 3) & 1) * 8;  // + mt*16
    const int a_sh  = lane >> 4;                                      // seg half
    const int b_row = wn * 32 + (lane & 7);                           // + nt*8
    const int b_sh  = (lane >> 3) & 1;

    float acc[4][4][4];
    #pragma unroll
    for (int mt = 0; mt < 4; mt++)
        #pragma unroll
        for (int nt = 0; nt < 4; nt++)
            #pragma unroll
            for (int r = 0; r < 4; r++) acc[mt][nt][r] = 0.f;

    // preload head 0
    load_tile(sm,              g_Abf + ((size_t)0 * NPADc + n0) * Ec);
    load_tile(sm + TILE_BYTES, g_Bbf + ((size_t)0 * NPADc + m0) * Ec);
    __syncthreads();

    #pragma unroll 1
    for (int h = 0; h < Hc; h++) {
        const int p = h & 1;
        const uint32_t Ab = abase + p * BUF_BYTES;
        const uint32_t Bb = Ab + TILE_BYTES;

        // prefetch next head into the other buffer (overlaps with compute)
        if (h < Hc - 1) {
            const int q = 1 - p;
            load_tile(sm + q * BUF_BYTES,
                      g_Abf + ((size_t)(h + 1) * NPADc + n0) * Ec);
            load_tile(sm + q * BUF_BYTES + TILE_BYTES,
                      g_Bbf + ((size_t)(h + 1) * NPADc + m0) * Ec);
        }

        float sim[4][4][4];
        #pragma unroll
        for (int mt = 0; mt < 4; mt++)
            #pragma unroll
            for (int nt = 0; nt < 4; nt++)
                #pragma unroll
                for (int r = 0; r < 4; r++) sim[mt][nt][r] = 0.f;

        #pragma unroll
        for (int k = 0; k < 4; k++) {
            uint32_t afr[4][4];
            #pragma unroll
            for (int mt = 0; mt < 4; mt++) {
                uint32_t off = (uint32_t)(a_row + mt * 16) * 128 + (k * 2 + a_sh) * 16;
                uint32_t sw = off ^ ((off >> 3) & 0x70);
                ldsm_x4(afr[mt], Ab + sw);
            }
            uint32_t bfr[4][2];
            #pragma unroll
            for (int nt = 0; nt < 4; nt++) {
                uint32_t off = (uint32_t)(b_row + nt * 8) * 128 + (k * 2 + b_sh) * 16;
                uint32_t sw = off ^ ((off >> 3) & 0x70);
                ldsm_x2(bfr[nt], Bb + sw);
            }
            #pragma unroll
            for (int mt = 0; mt < 4; mt++)
                #pragma unroll
                for (int nt = 0; nt < 4; nt++)
                    mma_bf16(sim[mt][nt], afr[mt], bfr[nt]);
        }

        #pragma unroll
        for (int mt = 0; mt < 4; mt++)
            #pragma unroll
            for (int nt = 0; nt < 4; nt++)
                #pragma unroll
                for (int r = 0; r < 4; r++)
                    acc[mt][nt][r] += sigmoid_poly(sim[mt][nt][r]);

        __syncthreads();
    }

    // epilogue: direct stores (pairs of consecutive cols per thread)
    const int g = lane >> 2;
    const int tig = lane & 3;
    #pragma unroll
    for (int mt = 0; mt < 4; mt++) {
        int gn0 = n0 + wm * 64 + mt * 16 + g;
        #pragma unroll
        for (int nt = 0; nt < 4; nt++) {
            int gm = m0 + wn * 32 + nt * 8 + tig * 2;
            if (gm < NNc) {
                if (gn0 < NNc) {
                    float2 v = make_float2(acc[mt][nt][0] * 0.125f,
                                           acc[mt][nt][1] * 0.125f);
                    *(float2*)&adj[(size_t)gn0 * NNc + gm] = v;
                }
                if (gn0 + 8 < NNc) {
                    float2 v = make_float2(acc[mt][nt][2] * 0.125f,
                                           acc[mt][nt][3] * 0.125f);
                    *(float2*)&adj[(size_t)(gn0 + 8) * NNc + gm] = v;
                }
            }
        }
    }
}

// =====================================================================
// launch
// =====================================================================
extern "C" void kernel_launch(void* const* d_in, const int* in_sizes, int n_in,
                              void* d_out, int out_size) {
    (void)in_sizes; (void)n_in; (void)out_size;
    const float* lm_X     = (const float*)d_in[0];
    const float* lm_Y     = (const float*)d_in[1];
    const float* tg_X     = (const float*)d_in[2];
    const float* lm_delay = (const float*)d_in[4];
    const float* tg_delay = (const float*)d_in[5];
    const float* W_emb    = (const float*)d_in[6];
    const float* b_emb    = (const float*)d_in[7];
    const float* w1       = (const float*)d_in[8];
    const float* w2       = (const float*)d_in[9];

    float* out     = (float*)d_out;
    float* y_pred  = out;                       // [2000, 2]
    float* adj     = out + 4000;                // [4000, 4000]
    float* teacher = adj + (size_t)NNc * NNc;   // [4000, 4000]

    static int smem_set = 0;
    const int ADJ_SMEM = 2 * BUF_BYTES + 1024;  // 66560
    if (!smem_set) {
        cudaFuncSetAttribute(adj_mm_kernel,
                             cudaFuncAttributeMaxDynamicSharedMemorySize, ADJ_SMEM);
        smem_set = 1;
    }

    fill_teacher_kernel<<<dim3(4, NNc), 256>>>(teacher);
    sq_kernel<<<8, 256>>>(lm_X);
    xt_kernel<<<(Ec * MPADc + 255) / 256, 256>>>(lm_X);
    embed_kernel<<<NPADc, 64>>>(lm_X, tg_X, lm_delay, tg_delay,
                                W_emb, b_emb, w1, w2);
    d2_kernel<<<dim3(32, 32), 256>>>();
    topk_kernel<<<N1c, 256>>>(lm_Y, y_pred, teacher);
    adj_mm_kernel<<<dim3(32, 32), 256, ADJ_SMEM>>>(adj);
}

// round 4
// speedup vs baseline: 4.2556x; 1.1269x over previous
#include <cuda_runtime.h>
#include <cuda_bf16.h>
#include <cstdint>

// Problem constants (fixed instance)
#define N1c 2000     // landmarks
#define NNc 4000     // total nodes
#define NPADc 4096   // padded node count
#define Dc 63        // feature dim
#define Ec 64        // embedding dim
#define Hc 8         // heads
#define KNNc 5
#define MPADc 2048   // padded col count for d2 matrix

// -------- device scratch (no allocations allowed) --------
__device__ __nv_bfloat16 g_Abf[(size_t)Hc * NPADc * Ec];  // [h][n][e] normalized a (bf16)
__device__ __nv_bfloat16 g_Bbf[(size_t)Hc * NPADc * Ec];  // [h][n][e] normalized b (bf16)
__device__ float g_sq[N1c];                               // row squared norms of lm_X
__device__ float g_XT[Ec * MPADc];                        // lm_X transposed [64][2048]
__device__ float g_d2[(size_t)N1c * MPADc];               // pairwise squared distances

__device__ __forceinline__ uint32_t smem_u32(const void* p) {
    uint32_t a;
    asm("{ .reg .u64 t; cvta.to.shared.u64 t, %1; cvt.u32.u64 %0, t; }"
        : "=r"(a) : "l"(p));
    return a;
}

// -------- packed f32x2 helpers (sm_100-family PTX, base target) --------
__device__ __forceinline__ uint64_t pk2(float lo, float hi) {
    uint64_t r;
    asm("mov.b64 %0, {%1, %2};" : "=l"(r) : "f"(lo), "f"(hi));
    return r;
}
__device__ __forceinline__ uint64_t f2mul(uint64_t a, uint64_t b) {
    uint64_t d;
    asm("mul.rn.f32x2 %0, %1, %2;" : "=l"(d) : "l"(a), "l"(b));
    return d;
}
__device__ __forceinline__ uint64_t f2fma(uint64_t a, uint64_t b, uint64_t c) {
    uint64_t d;
    asm("fma.rn.f32x2 %0, %1, %2, %3;" : "=l"(d) : "l"(a), "l"(b), "l"(c));
    return d;
}
__device__ __forceinline__ uint64_t f2add(uint64_t a, uint64_t b) {
    uint64_t d;
    asm("add.rn.f32x2 %0, %1, %2;" : "=l"(d) : "l"(a), "l"(b));
    return d;
}

// =====================================================================
// teacher adjacency fill
// =====================================================================
__global__ void fill_teacher_kernel(float* __restrict__ t) {
    int j = (blockIdx.x * 256 + threadIdx.x) * 4;
    int i = blockIdx.y;
    if (j < NNc) {
        float v = ((i < N1c) != (j < N1c)) ? 1.0f : 0.0f;
        *(float4*)&t[(size_t)i * NNc + j] = make_float4(v, v, v, v);
    }
}

// =====================================================================
// squared norms of landmark rows
// =====================================================================
__global__ void sq_kernel(const float* __restrict__ lm_X) {
    int n = blockIdx.x * blockDim.x + threadIdx.x;
    if (n < N1c) {
        float s = 0.f;
        #pragma unroll
        for (int k = 0; k < Dc; k++) {
            float x = lm_X[n * Dc + k];
            s = fmaf(x, x, s);
        }
        g_sq[n] = s;
    }
}

// =====================================================================
// transpose lm_X -> g_XT [64][2048] (row 63 and n>=2000 zero)
// =====================================================================
__global__ void xt_kernel(const float* __restrict__ lm_X) {
    int idx = blockIdx.x * 256 + threadIdx.x;
    if (idx < Ec * MPADc) {
        int k = idx / MPADc;
        int n = idx % MPADc;
        g_XT[idx] = (k < Dc && n < N1c) ? lm_X[n * Dc + k] : 0.f;
    }
}

// =====================================================================
// embedding + per-head normalized vectors: ONE WARP PER NODE.
// 256 threads = 8 nodes/block; norms via warp shuffles only.
// lane l computes e dims 2l, 2l+1.
// =====================================================================
__global__ void __launch_bounds__(256) embed_kernel(
        const float* __restrict__ lm_X,
        const float* __restrict__ tg_X,
        const float* __restrict__ lm_delay,
        const float* __restrict__ tg_delay,
        const float* __restrict__ W_emb,
        const float* __restrict__ b_emb,
        const float* __restrict__ w1,
        const float* __restrict__ w2) {
    __shared__ float Wsh[Ec * 65];
    __shared__ float feat[8][Ec];

    const int tid = threadIdx.x;
    const int lane = tid & 31;
    const int wp = tid >> 5;
    const int n = blockIdx.x * 8 + wp;

    // load W_emb (row j padded to 65)
    for (int idx = tid; idx < Ec * Ec; idx += 256)
        Wsh[(idx >> 6) * 65 + (idx & 63)] = W_emb[idx];

    const bool pad = (n >= NNc);
    if (!pad) {
        const float* src = (n < N1c) ? lm_X + (size_t)n * Dc
                                     : tg_X + (size_t)(n - N1c) * Dc;
        float dly = (n < N1c) ? lm_delay[n] : tg_delay[n - N1c];
        feat[wp][lane] = src[lane];
        feat[wp][lane + 32] = (lane < 31) ? src[lane + 32] : dly;
    }
    __syncthreads();

    if (pad) {
        const __nv_bfloat162 z = __floats2bfloat162_rn(0.f, 0.f);
        #pragma unroll
        for (int h = 0; h < Hc; h++) {
            *(__nv_bfloat162*)&g_Abf[((size_t)h * NPADc + n) * Ec + 2 * lane] = z;
            *(__nv_bfloat162*)&g_Bbf[((size_t)h * NPADc + n) * Ec + 2 * lane] = z;
        }
        return;
    }

    const int j0 = 2 * lane, j1 = 2 * lane + 1;
    float e0 = b_emb[j0], e1 = b_emb[j1];
    const float* W0 = &Wsh[j0 * 65];
    const float* W1 = &Wsh[j1 * 65];
    #pragma unroll
    for (int k = 0; k < Ec; k++) {
        float f = feat[wp][k];
        e0 = fmaf(W0[k], f, e0);
        e1 = fmaf(W1[k], f, e1);
    }

    #pragma unroll 1
    for (int h = 0; h < Hc; h++) {
        float a0 = e0 * w1[j0 * Hc + h];
        float a1 = e1 * w1[j1 * Hc + h];
        float b0 = e0 * w2[j0 * Hc + h];
        float b1 = e1 * w2[j1 * Hc + h];

        float va = fmaf(a0, a0, a1 * a1);
        float vb = fmaf(b0, b0, b1 * b1);
        #pragma unroll
        for (int o = 16; o > 0; o >>= 1) {
            va += __shfl_xor_sync(0xffffffffu, va, o);
            vb += __shfl_xor_sync(0xffffffffu, vb, o);
        }
        float ra = rsqrtf(va);
        float rb = rsqrtf(vb);

        *(__nv_bfloat162*)&g_Abf[((size_t)h * NPADc + n) * Ec + j0] =
            __floats2bfloat162_rn(a0 * ra, a1 * ra);
        *(__nv_bfloat162*)&g_Bbf[((size_t)h * NPADc + n) * Ec + j0] =
            __floats2bfloat162_rn(b0 * rb, b1 * rb);
    }
}

// =====================================================================
// d2 GEMM, symmetric: only upper-tri 64x64 tiles computed (528 blocks);
// off-diagonal tiles mirrored via smem transpose.
// =====================================================================
__global__ void __launch_bounds__(256) d2_kernel() {
    __shared__ float As[Ec][64];
    __shared__ float Bs[Ec][65];   // reused as transpose staging

    const int tid = threadIdx.x;
    const int tx = tid >> 4, ty = tid & 15;

    // decode linear block id -> upper-tri pair (bx >= by)
    int bid = blockIdx.x;
    int bx = (int)((sqrtf(8.f * (float)bid + 1.f) - 1.f) * 0.5f);
    while ((bx + 1) * (bx + 2) / 2 <= bid) bx++;
    while (bx * (bx + 1) / 2 > bid) bx--;
    int by = bid - bx * (bx + 1) / 2;

    const int n0 = by * 64;   // row tile
    const int m0 = bx * 64;   // col tile (m0 >= n0)

    #pragma unroll
    for (int p = 0; p < 16; p++) {
        int idx = p * 256 + tid;
        int k = idx >> 6, r = idx & 63;
        As[k][r] = g_XT[k * MPADc + n0 + r];
        Bs[k][r] = g_XT[k * MPADc + m0 + r];
    }
    __syncthreads();

    float dot[4][4];
    #pragma unroll
    for (int i = 0; i < 4; i++)
        #pragma unroll
        for (int j = 0; j < 4; j++) dot[i][j] = 0.f;

    #pragma unroll 16
    for (int k = 0; k < Ec; k++) {
        float a[4], b[4];
        #pragma unroll
        for (int i = 0; i < 4; i++) a[i] = As[k][tx * 4 + i];
        #pragma unroll
        for (int j = 0; j < 4; j++) b[j] = Bs[k][ty * 4 + j];
        #pragma unroll
        for (int i = 0; i < 4; i++)
            #pragma unroll
            for (int j = 0; j < 4; j++)
                dot[i][j] = fmaf(a[i], b[j], dot[i][j]);
    }

    const float INF = __int_as_float(0x7f800000);
    float v[4][4];
    #pragma unroll
    for (int i = 0; i < 4; i++) {
        int nn = n0 + tx * 4 + i;
        float sqn = (nn < N1c) ? g_sq[nn] : 0.f;
        #pragma unroll
        for (int j = 0; j < 4; j++) {
            int mm = m0 + ty * 4 + j;
            float val = INF;
            if (nn < N1c && mm < N1c && mm != nn)
                val = fmaxf(sqn + g_sq[mm] - 2.f * dot[i][j], 0.f);
            v[i][j] = val;
        }
    }

    // write normal orientation (rows n, cols m) — float4 per thread-row
    #pragma unroll
    for (int i = 0; i < 4; i++) {
        int nn = n0 + tx * 4 + i;
        if (nn < N1c)
            *(float4*)&g_d2[(size_t)nn * MPADc + m0 + ty * 4] =
                make_float4(v[i][0], v[i][1], v[i][2], v[i][3]);
    }

    if (bx == by) return;

    // mirror: stage into Bs (now free), write transposed coalesced
    __syncthreads();
    #pragma unroll
    for (int i = 0; i < 4; i++)
        #pragma unroll
        for (int j = 0; j < 4; j++)
            Bs[tx * 4 + i][ty * 4 + j] = v[i][j];
    __syncthreads();

    #pragma unroll
    for (int i = 0; i < 4; i++) {
        int mm = m0 + tx * 4 + i;       // output row (col tile index)
        if (mm < N1c) {
            float4 o;
            o.x = Bs[ty * 4 + 0][tx * 4 + i];
            o.y = Bs[ty * 4 + 1][tx * 4 + i];
            o.z = Bs[ty * 4 + 2][tx * 4 + i];
            o.w = Bs[ty * 4 + 3][tx * 4 + i];
            *(float4*)&g_d2[(size_t)mm * MPADc + n0 + ty * 4] = o;
        }
    }
}

// =====================================================================
// top-5 per row from d2 matrix; y_pred + teacher scatter.
// warp-shuffle min + tiny smem step (2 syncs per round).
// =====================================================================
__global__ void topk_kernel(const float* __restrict__ lm_Y,
                            float* __restrict__ y_pred,
                            float* __restrict__ teacher) {
    __shared__ unsigned long long wmin[8];
    __shared__ unsigned long long swin;
    const int n = blockIdx.x;
    const int tid = threadIdx.x;
    const int lane = tid & 31;
    const int wp = tid >> 5;
    const float INF = __int_as_float(0x7f800000);

    float bd[KNNc];
    int   bi[KNNc];
    #pragma unroll
    for (int t = 0; t < KNNc; t++) { bd[t] = INF; bi[t] = 0; }

    #pragma unroll
    for (int it = 0; it < 8; it++) {
        int m = it * 256 + tid;
        float d2 = g_d2[(size_t)n * MPADc + m];
        if (d2 < bd[KNNc - 1]) {
            bd[KNNc - 1] = d2; bi[KNNc - 1] = m;
            #pragma unroll
            for (int t = KNNc - 1; t > 0; t--) {
                if (bd[t] < bd[t - 1]) {
                    float td = bd[t]; bd[t] = bd[t - 1]; bd[t - 1] = td;
                    int   ti = bi[t]; bi[t] = bi[t - 1]; bi[t - 1] = ti;
                }
            }
        }
    }

    float y0 = 0.f, y1 = 0.f;
    #pragma unroll 1
    for (int r = 0; r < KNNc; r++) {
        unsigned long long key =
            (((unsigned long long)__float_as_uint(bd[0])) << 32) | (unsigned)bi[0];
        unsigned long long wk = key;
        #pragma unroll
        for (int o = 16; o > 0; o >>= 1) {
            unsigned long long t = __shfl_xor_sync(0xffffffffu, wk, o);
            if (t < wk) wk = t;
        }
        if (lane == 0) wmin[wp] = wk;
        __syncthreads();
        if (tid == 0) {
            unsigned long long m = wmin[0];
            #pragma unroll
            for (int i = 1; i < 8; i++) if (wmin[i] < m) m = wmin[i];
            swin = m;
        }
        __syncthreads();
        unsigned long long win = swin;
        int wm = (int)(win & 0xffffffffull);
        if (key == win) {
            #pragma unroll
            for (int t = 0; t < KNNc - 1; t++) { bd[t] = bd[t + 1]; bi[t] = bi[t + 1]; }
            bd[KNNc - 1] = INF; bi[KNNc - 1] = 0;
        }
        if (tid == 0) {
            teacher[(size_t)n * NNc + wm] = 1.0f;
            y0 += lm_Y[wm * 2 + 0];
            y1 += lm_Y[wm * 2 + 1];
        }
    }
    if (tid == 0) {
        y_pred[n * 2 + 0] = y0 * 0.2f;
        y_pred[n * 2 + 1] = y1 * 0.2f;
    }
}

// =====================================================================
// HMMA adjacency kernel: 128x128 tile per CTA, 8 warps (2 x 4),
// mma.sync.m16n8k16 bf16; sigmoid via packed f32x2 degree-9 odd poly.
// =====================================================================
#define TILE_BYTES 16384            // 128 rows x 128B
#define BUF_BYTES  (2 * TILE_BYTES) // A + B per stage

__device__ __forceinline__ void ldsm_x4(uint32_t* r, uint32_t addr) {
    asm volatile("ldmatrix.sync.aligned.m8n8.x4.shared.b16 {%0,%1,%2,%3}, [%4];"
                 : "=r"(r[0]), "=r"(r[1]), "=r"(r[2]), "=r"(r[3]) : "r"(addr));
}
__device__ __forceinline__ void ldsm_x2(uint32_t* r, uint32_t addr) {
    asm volatile("ldmatrix.sync.aligned.m8n8.x2.shared.b16 {%0,%1}, [%2];"
                 : "=r"(r[0]), "=r"(r[1]) : "r"(addr));
}
__device__ __forceinline__ void mma_bf16(float* c, const uint32_t* a,
                                         const uint32_t* b) {
    asm volatile(
        "mma.sync.aligned.m16n8k16.row.col.f32.bf16.bf16.f32 "
        "{%0,%1,%2,%3}, {%4,%5,%6,%7}, {%8,%9}, {%0,%1,%2,%3};"
        : "+f"(c[0]), "+f"(c[1]), "+f"(c[2]), "+f"(c[3])
        : "r"(a[0]), "r"(a[1]), "r"(a[2]), "r"(a[3]), "r"(b[0]), "r"(b[1]));
}

__global__ void __launch_bounds__(256, 1) adj_mm_kernel(float* __restrict__ adj) {
    extern __shared__ char dsm[];
    uint32_t dbase = smem_u32(dsm);
    uint32_t abase = (dbase + 1023u) & ~1023u;
    char* sm = dsm + (abase - dbase);

    const int tid = threadIdx.x;
    const int lane = tid & 31;
    const int wid = tid >> 5;
    const int wm = wid & 1;    // 2 warp-rows of 64
    const int wn = wid >> 1;   // 4 warp-cols of 32
    const int n0 = blockIdx.y * 128;
    const int m0 = blockIdx.x * 128;

    auto load_tile = [&](char* dst, const __nv_bfloat16* src) {
        #pragma unroll
        for (int p = 0; p < 4; p++) {
            int row = p * 32 + (tid >> 3);
            int seg = tid & 7;
            uint32_t off = row * 128 + seg * 16;
            uint32_t sw = off ^ ((off >> 3) & 0x70);
            *(uint4*)(dst + sw) =
                *(const uint4*)((const char*)(src + (size_t)row * Ec) + seg * 16);
        }
    };

    const int a_row = wm * 64 + (lane & 7) + ((lane >> 3) & 1) * 8;
    const int a_sh  = lane >> 4;
    const int b_row = wn * 32 + (lane & 7);
    const int b_sh  = (lane >> 3) & 1;

    // packed poly constants
    const uint64_t C9 = pk2(2.1356922e-5f, 2.1356922e-5f);
    const uint64_t C7 = pk2(-2.1081349e-4f, -2.1081349e-4f);
    const uint64_t C5 = pk2(2.0833333e-3f, 2.0833333e-3f);
    const uint64_t C3 = pk2(-2.0833334e-2f, -2.0833334e-2f);
    const uint64_t C1 = pk2(0.25f, 0.25f);
    const uint64_t HALF = pk2(0.5f, 0.5f);

    uint64_t acc2[4][4][2];
    #pragma unroll
    for (int mt = 0; mt < 4; mt++)
        #pragma unroll
        for (int nt = 0; nt < 4; nt++) {
            acc2[mt][nt][0] = 0ull;
            acc2[mt][nt][1] = 0ull;
        }

    load_tile(sm,              g_Abf + ((size_t)0 * NPADc + n0) * Ec);
    load_tile(sm + TILE_BYTES, g_Bbf + ((size_t)0 * NPADc + m0) * Ec);
    __syncthreads();

    #pragma unroll 1
    for (int h = 0; h < Hc; h++) {
        const int p = h & 1;
        const uint32_t Ab = abase + p * BUF_BYTES;
        const uint32_t Bb = Ab + TILE_BYTES;

        if (h < Hc - 1) {
            const int q = 1 - p;
            load_tile(sm + q * BUF_BYTES,
                      g_Abf + ((size_t)(h + 1) * NPADc + n0) * Ec);
            load_tile(sm + q * BUF_BYTES + TILE_BYTES,
                      g_Bbf + ((size_t)(h + 1) * NPADc + m0) * Ec);
        }

        float sim[4][4][4];
        #pragma unroll
        for (int mt = 0; mt < 4; mt++)
            #pragma unroll
            for (int nt = 0; nt < 4; nt++)
                #pragma unroll
                for (int r = 0; r < 4; r++) sim[mt][nt][r] = 0.f;

        #pragma unroll
        for (int k = 0; k < 4; k++) {
            uint32_t afr[4][4];
            #pragma unroll
            for (int mt = 0; mt < 4; mt++) {
                uint32_t off = (uint32_t)(a_row + mt * 16) * 128 + (k * 2 + a_sh) * 16;
                uint32_t sw = off ^ ((off >> 3) & 0x70);
                ldsm_x4(afr[mt], Ab + sw);
            }
            uint32_t bfr[4][2];
            #pragma unroll
            for (int nt = 0; nt < 4; nt++) {
                uint32_t off = (uint32_t)(b_row + nt * 8) * 128 + (k * 2 + b_sh) * 16;
                uint32_t sw = off ^ ((off >> 3) & 0x70);
                ldsm_x2(bfr[nt], Bb + sw);
            }
            #pragma unroll
            for (int mt = 0; mt < 4; mt++)
                #pragma unroll
                for (int nt = 0; nt < 4; nt++)
                    mma_bf16(sim[mt][nt], afr[mt], bfr[nt]);
        }

        // packed sigmoid + accumulate
        #pragma unroll
        for (int mt = 0; mt < 4; mt++)
            #pragma unroll
            for (int nt = 0; nt < 4; nt++) {
                #pragma unroll
                for (int half = 0; half < 2; half++) {
                    uint64_t x = pk2(sim[mt][nt][half * 2],
                                     sim[mt][nt][half * 2 + 1]);
                    uint64_t u = f2mul(x, x);
                    uint64_t pp = f2fma(u, C9, C7);
                    pp = f2fma(u, pp, C5);
                    pp = f2fma(u, pp, C3);
                    pp = f2fma(u, pp, C1);
                    acc2[mt][nt][half] =
                        f2add(acc2[mt][nt][half], f2fma(x, pp, HALF));
                }
            }

        __syncthreads();
    }

    // epilogue: scale by 1/8 (packed), store as 8-byte float2
    const uint64_t SCALE = pk2(0.125f, 0.125f);
    const int g = lane >> 2;
    const int tig = lane & 3;
    #pragma unroll
    for (int mt = 0; mt < 4; mt++) {
        int gn0 = n0 + wm * 64 + mt * 16 + g;
        #pragma unroll
        for (int nt = 0; nt < 4; nt++) {
            int gm = m0 + wn * 32 + nt * 8 + tig * 2;
            if (gm < NNc) {
                if (gn0 < NNc) {
                    uint64_t v = f2mul(acc2[mt][nt][0], SCALE);
                    *(uint64_t*)&adj[(size_t)gn0 * NNc + gm] = v;
                }
                if (gn0 + 8 < NNc) {
                    uint64_t v = f2mul(acc2[mt][nt][1], SCALE);
                    *(uint64_t*)&adj[(size_t)(gn0 + 8) * NNc + gm] = v;
                }
            }
        }
    }
}

// =====================================================================
// launch
// =====================================================================
extern "C" void kernel_launch(void* const* d_in, const int* in_sizes, int n_in,
                              void* d_out, int out_size) {
    (void)in_sizes; (void)n_in; (void)out_size;
    const float* lm_X     = (const float*)d_in[0];
    const float* lm_Y     = (const float*)d_in[1];
    const float* tg_X     = (const float*)d_in[2];
    const float* lm_delay = (const float*)d_in[4];
    const float* tg_delay = (const float*)d_in[5];
    const float* W_emb    = (const float*)d_in[6];
    const float* b_emb    = (const float*)d_in[7];
    const float* w1       = (const float*)d_in[8];
    const float* w2       = (const float*)d_in[9];

    float* out     = (float*)d_out;
    float* y_pred  = out;                       // [2000, 2]
    float* adj     = out + 4000;                // [4000, 4000]
    float* teacher = adj + (size_t)NNc * NNc;   // [4000, 4000]

    static int smem_set = 0;
    const int ADJ_SMEM = 2 * BUF_BYTES + 1024;  // 66560
    if (!smem_set) {
        cudaFuncSetAttribute(adj_mm_kernel,
                             cudaFuncAttributeMaxDynamicSharedMemorySize, ADJ_SMEM);
        smem_set = 1;
    }

    fill_teacher_kernel<<<dim3(4, NNc), 256>>>(teacher);
    sq_kernel<<<8, 256>>>(lm_X);
    xt_kernel<<<(Ec * MPADc + 255) / 256, 256>>>(lm_X);
    embed_kernel<<<512, 256>>>(lm_X, tg_X, lm_delay, tg_delay,
                               W_emb, b_emb, w1, w2);
    d2_kernel<<<528, 256>>>();
    topk_kernel<<<N1c, 256>>>(lm_Y, y_pred, teacher);
    adj_mm_kernel<<<dim3(32, 32), 256, ADJ_SMEM>>>(adj);
}

// round 5
// speedup vs baseline: 4.8264x; 1.1341x over previous
#include <cuda_runtime.h>
#include <cuda_bf16.h>
#include <cstdint>

// Problem constants (fixed instance)
#define N1c 2000     // landmarks
#define NNc 4000     // total nodes
#define NPADc 4096   // padded node count
#define Dc 63        // feature dim
#define Ec 64        // embedding dim
#define Hc 8         // heads
#define KNNc 5
#define MPADc 2048   // padded col count for d2 matrix

// -------- device scratch (no allocations allowed) --------
__device__ __nv_bfloat16 g_Abf[(size_t)Hc * NPADc * Ec];  // [h][n][e] normalized a (bf16)
__device__ __nv_bfloat16 g_Bbf[(size_t)Hc * NPADc * Ec];  // [h][n][e] normalized b (bf16)
__device__ float g_sq[N1c];                               // row squared norms of lm_X
__device__ float g_XT[Ec * MPADc];                        // lm_X transposed [64][2048]
__device__ float g_d2[(size_t)N1c * MPADc];               // pairwise squared distances

__device__ __forceinline__ uint32_t smem_u32(const void* p) {
    uint32_t a;
    asm("{ .reg .u64 t; cvta.to.shared.u64 t, %1; cvt.u32.u64 %0, t; }"
        : "=r"(a) : "l"(p));
    return a;
}

// -------- packed f32x2 helpers --------
__device__ __forceinline__ uint64_t pk2(float lo, float hi) {
    uint64_t r;
    asm("mov.b64 %0, {%1, %2};" : "=l"(r) : "f"(lo), "f"(hi));
    return r;
}
__device__ __forceinline__ uint64_t f2mul(uint64_t a, uint64_t b) {
    uint64_t d;
    asm("mul.rn.f32x2 %0, %1, %2;" : "=l"(d) : "l"(a), "l"(b));
    return d;
}
__device__ __forceinline__ uint64_t f2fma(uint64_t a, uint64_t b, uint64_t c) {
    uint64_t d;
    asm("fma.rn.f32x2 %0, %1, %2, %3;" : "=l"(d) : "l"(a), "l"(b), "l"(c));
    return d;
}
__device__ __forceinline__ uint64_t f2add(uint64_t a, uint64_t b) {
    uint64_t d;
    asm("add.rn.f32x2 %0, %1, %2;" : "=l"(d) : "l"(a), "l"(b));
    return d;
}

// =====================================================================
// teacher adjacency fill
// =====================================================================
__global__ void fill_teacher_kernel(float* __restrict__ t) {
    int j = (blockIdx.x * 256 + threadIdx.x) * 4;
    int i = blockIdx.y;
    if (j < NNc) {
        float v = ((i < N1c) != (j < N1c)) ? 1.0f : 0.0f;
        *(float4*)&t[(size_t)i * NNc + j] = make_float4(v, v, v, v);
    }
}

// =====================================================================
// squared norms of landmark rows
// =====================================================================
__global__ void sq_kernel(const float* __restrict__ lm_X) {
    int n = blockIdx.x * blockDim.x + threadIdx.x;
    if (n < N1c) {
        float s = 0.f;
        #pragma unroll
        for (int k = 0; k < Dc; k++) {
            float x = lm_X[n * Dc + k];
            s = fmaf(x, x, s);
        }
        g_sq[n] = s;
    }
}

// =====================================================================
// transpose lm_X -> g_XT [64][2048] (row 63 and n>=2000 zero)
// =====================================================================
__global__ void xt_kernel(const float* __restrict__ lm_X) {
    int idx = blockIdx.x * 256 + threadIdx.x;
    if (idx < Ec * MPADc) {
        int k = idx / MPADc;
        int n = idx % MPADc;
        g_XT[idx] = (k < Dc && n < N1c) ? lm_X[n * Dc + k] : 0.f;
    }
}

// =====================================================================
// embedding + per-head normalized vectors: one warp per node,
// head loop FULLY unrolled (16 independent shuffle chains -> ILP),
// w1/w2 staged transposed in smem.
// =====================================================================
__global__ void __launch_bounds__(256) embed_kernel(
        const float* __restrict__ lm_X,
        const float* __restrict__ tg_X,
        const float* __restrict__ lm_delay,
        const float* __restrict__ tg_delay,
        const float* __restrict__ W_emb,
        const float* __restrict__ b_emb,
        const float* __restrict__ w1,
        const float* __restrict__ w2) {
    __shared__ float Wsh[Ec * 65];
    __shared__ float w1T[Hc * Ec];   // [h][j]
    __shared__ float w2T[Hc * Ec];
    __shared__ float feat[8][Ec];

    const int tid = threadIdx.x;
    const int lane = tid & 31;
    const int wp = tid >> 5;
    const int n = blockIdx.x * 8 + wp;

    for (int idx = tid; idx < Ec * Ec; idx += 256)
        Wsh[(idx >> 6) * 65 + (idx & 63)] = W_emb[idx];
    for (int idx = tid; idx < Hc * Ec; idx += 256) {
        int h = idx & 7, j = idx >> 3;
        w1T[h * Ec + j] = w1[idx];
        w2T[h * Ec + j] = w2[idx];
    }

    const bool pad = (n >= NNc);
    if (!pad) {
        const float* src = (n < N1c) ? lm_X + (size_t)n * Dc
                                     : tg_X + (size_t)(n - N1c) * Dc;
        float dly = (n < N1c) ? lm_delay[n] : tg_delay[n - N1c];
        feat[wp][lane] = src[lane];
        feat[wp][lane + 32] = (lane < 31) ? src[lane + 32] : dly;
    }
    __syncthreads();

    if (pad) {
        const __nv_bfloat162 z = __floats2bfloat162_rn(0.f, 0.f);
        #pragma unroll
        for (int h = 0; h < Hc; h++) {
            *(__nv_bfloat162*)&g_Abf[((size_t)h * NPADc + n) * Ec + 2 * lane] = z;
            *(__nv_bfloat162*)&g_Bbf[((size_t)h * NPADc + n) * Ec + 2 * lane] = z;
        }
        return;
    }

    const int j0 = 2 * lane, j1 = 2 * lane + 1;
    float e0 = b_emb[j0], e1 = b_emb[j1];
    const float* W0 = &Wsh[j0 * 65];
    const float* W1 = &Wsh[j1 * 65];
    #pragma unroll
    for (int k = 0; k < Ec; k++) {
        float f = feat[wp][k];
        e0 = fmaf(W0[k], f, e0);
        e1 = fmaf(W1[k], f, e1);
    }

    // all heads' raw a/b values
    float a0[Hc], a1[Hc], b0[Hc], b1[Hc], va[Hc], vb[Hc];
    #pragma unroll
    for (int h = 0; h < Hc; h++) {
        float2 wa = *(const float2*)&w1T[h * Ec + j0];
        float2 wb = *(const float2*)&w2T[h * Ec + j0];
        a0[h] = e0 * wa.x; a1[h] = e1 * wa.y;
        b0[h] = e0 * wb.x; b1[h] = e1 * wb.y;
        va[h] = fmaf(a0[h], a0[h], a1[h] * a1[h]);
        vb[h] = fmaf(b0[h], b0[h], b1[h] * b1[h]);
    }
    // interleaved butterfly reductions: 16 independent chains
    #pragma unroll
    for (int o = 16; o > 0; o >>= 1) {
        #pragma unroll
        for (int h = 0; h < Hc; h++) {
            va[h] += __shfl_xor_sync(0xffffffffu, va[h], o);
            vb[h] += __shfl_xor_sync(0xffffffffu, vb[h], o);
        }
    }
    #pragma unroll
    for (int h = 0; h < Hc; h++) {
        float ra = rsqrtf(va[h]);
        float rb = rsqrtf(vb[h]);
        *(__nv_bfloat162*)&g_Abf[((size_t)h * NPADc + n) * Ec + j0] =
            __floats2bfloat162_rn(a0[h] * ra, a1[h] * ra);
        *(__nv_bfloat162*)&g_Bbf[((size_t)h * NPADc + n) * Ec + j0] =
            __floats2bfloat162_rn(b0[h] * rb, b1[h] * rb);
    }
}

// =====================================================================
// d2 GEMM, symmetric: only upper-tri 64x64 tiles (528 blocks)
// =====================================================================
__global__ void __launch_bounds__(256) d2_kernel() {
    __shared__ float As[Ec][64];
    __shared__ float Bs[Ec][65];

    const int tid = threadIdx.x;
    const int tx = tid >> 4, ty = tid & 15;

    int bid = blockIdx.x;
    int bx = (int)((sqrtf(8.f * (float)bid + 1.f) - 1.f) * 0.5f);
    while ((bx + 1) * (bx + 2) / 2 <= bid) bx++;
    while (bx * (bx + 1) / 2 > bid) bx--;
    int by = bid - bx * (bx + 1) / 2;

    const int n0 = by * 64;
    const int m0 = bx * 64;

    #pragma unroll
    for (int p = 0; p < 16; p++) {
        int idx = p * 256 + tid;
        int k = idx >> 6, r = idx & 63;
        As[k][r] = g_XT[k * MPADc + n0 + r];
        Bs[k][r] = g_XT[k * MPADc + m0 + r];
    }
    __syncthreads();

    float dot[4][4];
    #pragma unroll
    for (int i = 0; i < 4; i++)
        #pragma unroll
        for (int j = 0; j < 4; j++) dot[i][j] = 0.f;

    #pragma unroll 16
    for (int k = 0; k < Ec; k++) {
        float a[4], b[4];
        #pragma unroll
        for (int i = 0; i < 4; i++) a[i] = As[k][tx * 4 + i];
        #pragma unroll
        for (int j = 0; j < 4; j++) b[j] = Bs[k][ty * 4 + j];
        #pragma unroll
        for (int i = 0; i < 4; i++)
            #pragma unroll
            for (int j = 0; j < 4; j++)
                dot[i][j] = fmaf(a[i], b[j], dot[i][j]);
    }

    const float INF = __int_as_float(0x7f800000);
    float v[4][4];
    #pragma unroll
    for (int i = 0; i < 4; i++) {
        int nn = n0 + tx * 4 + i;
        float sqn = (nn < N1c) ? g_sq[nn] : 0.f;
        #pragma unroll
        for (int j = 0; j < 4; j++) {
            int mm = m0 + ty * 4 + j;
            float val = INF;
            if (nn < N1c && mm < N1c && mm != nn)
                val = fmaxf(sqn + g_sq[mm] - 2.f * dot[i][j], 0.f);
            v[i][j] = val;
        }
    }

    #pragma unroll
    for (int i = 0; i < 4; i++) {
        int nn = n0 + tx * 4 + i;
        if (nn < N1c)
            *(float4*)&g_d2[(size_t)nn * MPADc + m0 + ty * 4] =
                make_float4(v[i][0], v[i][1], v[i][2], v[i][3]);
    }

    if (bx == by) return;

    __syncthreads();
    #pragma unroll
    for (int i = 0; i < 4; i++)
        #pragma unroll
        for (int j = 0; j < 4; j++)
            Bs[tx * 4 + i][ty * 4 + j] = v[i][j];
    __syncthreads();

    #pragma unroll
    for (int i = 0; i < 4; i++) {
        int mm = m0 + tx * 4 + i;
        if (mm < N1c) {
            float4 o;
            o.x = Bs[ty * 4 + 0][tx * 4 + i];
            o.y = Bs[ty * 4 + 1][tx * 4 + i];
            o.z = Bs[ty * 4 + 2][tx * 4 + i];
            o.w = Bs[ty * 4 + 3][tx * 4 + i];
            *(float4*)&g_d2[(size_t)mm * MPADc + n0 + ty * 4] = o;
        }
    }
}

// =====================================================================
// top-5 per row from d2; y_pred + teacher scatter
// =====================================================================
__global__ void topk_kernel(const float* __restrict__ lm_Y,
                            float* __restrict__ y_pred,
                            float* __restrict__ teacher) {
    __shared__ unsigned long long wmin[8];
    __shared__ unsigned long long swin;
    const int n = blockIdx.x;
    const int tid = threadIdx.x;
    const int lane = tid & 31;
    const int wp = tid >> 5;
    const float INF = __int_as_float(0x7f800000);

    float bd[KNNc];
    int   bi[KNNc];
    #pragma unroll
    for (int t = 0; t < KNNc; t++) { bd[t] = INF; bi[t] = 0; }

    #pragma unroll
    for (int it = 0; it < 8; it++) {
        int m = it * 256 + tid;
        float d2 = g_d2[(size_t)n * MPADc + m];
        if (d2 < bd[KNNc - 1]) {
            bd[KNNc - 1] = d2; bi[KNNc - 1] = m;
            #pragma unroll
            for (int t = KNNc - 1; t > 0; t--) {
                if (bd[t] < bd[t - 1]) {
                    float td = bd[t]; bd[t] = bd[t - 1]; bd[t - 1] = td;
                    int   ti = bi[t]; bi[t] = bi[t - 1]; bi[t - 1] = ti;
                }
            }
        }
    }

    float y0 = 0.f, y1 = 0.f;
    #pragma unroll 1
    for (int r = 0; r < KNNc; r++) {
        unsigned long long key =
            (((unsigned long long)__float_as_uint(bd[0])) << 32) | (unsigned)bi[0];
        unsigned long long wk = key;
        #pragma unroll
        for (int o = 16; o > 0; o >>= 1) {
            unsigned long long t = __shfl_xor_sync(0xffffffffu, wk, o);
            if (t < wk) wk = t;
        }
        if (lane == 0) wmin[wp] = wk;
        __syncthreads();
        if (tid == 0) {
            unsigned long long m = wmin[0];
            #pragma unroll
            for (int i = 1; i < 8; i++) if (wmin[i] < m) m = wmin[i];
            swin = m;
        }
        __syncthreads();
        unsigned long long win = swin;
        int wm = (int)(win & 0xffffffffull);
        if (key == win) {
            #pragma unroll
            for (int t = 0; t < KNNc - 1; t++) { bd[t] = bd[t + 1]; bi[t] = bi[t + 1]; }
            bd[KNNc - 1] = INF; bi[KNNc - 1] = 0;
        }
        if (tid == 0) {
            teacher[(size_t)n * NNc + wm] = 1.0f;
            y0 += lm_Y[wm * 2 + 0];
            y1 += lm_Y[wm * 2 + 1];
        }
    }
    if (tid == 0) {
        y_pred[n * 2 + 0] = y0 * 0.2f;
        y_pred[n * 2 + 1] = y1 * 0.2f;
    }
}

// =====================================================================
// HMMA adjacency kernel (unchanged from R4)
// =====================================================================
#define TILE_BYTES 16384
#define BUF_BYTES  (2 * TILE_BYTES)

__device__ __forceinline__ void ldsm_x4(uint32_t* r, uint32_t addr) {
    asm volatile("ldmatrix.sync.aligned.m8n8.x4.shared.b16 {%0,%1,%2,%3}, [%4];"
                 : "=r"(r[0]), "=r"(r[1]), "=r"(r[2]), "=r"(r[3]) : "r"(addr));
}
__device__ __forceinline__ void ldsm_x2(uint32_t* r, uint32_t addr) {
    asm volatile("ldmatrix.sync.aligned.m8n8.x2.shared.b16 {%0,%1}, [%2];"
                 : "=r"(r[0]), "=r"(r[1]) : "r"(addr));
}
__device__ __forceinline__ void mma_bf16(float* c, const uint32_t* a,
                                         const uint32_t* b) {
    asm volatile(
        "mma.sync.aligned.m16n8k16.row.col.f32.bf16.bf16.f32 "
        "{%0,%1,%2,%3}, {%4,%5,%6,%7}, {%8,%9}, {%0,%1,%2,%3};"
        : "+f"(c[0]), "+f"(c[1]), "+f"(c[2]), "+f"(c[3])
        : "r"(a[0]), "r"(a[1]), "r"(a[2]), "r"(a[3]), "r"(b[0]), "r"(b[1]));
}

__global__ void __launch_bounds__(256, 1) adj_mm_kernel(float* __restrict__ adj) {
    extern __shared__ char dsm[];
    uint32_t dbase = smem_u32(dsm);
    uint32_t abase = (dbase + 1023u) & ~1023u;
    char* sm = dsm + (abase - dbase);

    const int tid = threadIdx.x;
    const int lane = tid & 31;
    const int wid = tid >> 5;
    const int wm = wid & 1;
    const int wn = wid >> 1;
    const int n0 = blockIdx.y * 128;
    const int m0 = blockIdx.x * 128;

    auto load_tile = [&](char* dst, const __nv_bfloat16* src) {
        #pragma unroll
        for (int p = 0; p < 4; p++) {
            int row = p * 32 + (tid >> 3);
            int seg = tid & 7;
            uint32_t off = row * 128 + seg * 16;
            uint32_t sw = off ^ ((off >> 3) & 0x70);
            *(uint4*)(dst + sw) =
                *(const uint4*)((const char*)(src + (size_t)row * Ec) + seg * 16);
        }
    };

    const int a_row = wm * 64 + (lane & 7) + ((lane >> 3) & 1) * 8;
    const int a_sh  = lane >> 4;
    const int b_row = wn * 32 + (lane & 7);
    const int b_sh  = (lane >> 3) & 1;

    const uint64_t C9 = pk2(2.1356922e-5f, 2.1356922e-5f);
    const uint64_t C7 = pk2(-2.1081349e-4f, -2.1081349e-4f);
    const uint64_t C5 = pk2(2.0833333e-3f, 2.0833333e-3f);
    const uint64_t C3 = pk2(-2.0833334e-2f, -2.0833334e-2f);
    const uint64_t C1 = pk2(0.25f, 0.25f);
    const uint64_t HALF = pk2(0.5f, 0.5f);

    uint64_t acc2[4][4][2];
    #pragma unroll
    for (int mt = 0; mt < 4; mt++)
        #pragma unroll
        for (int nt = 0; nt < 4; nt++) {
            acc2[mt][nt][0] = 0ull;
            acc2[mt][nt][1] = 0ull;
        }

    load_tile(sm,              g_Abf + ((size_t)0 * NPADc + n0) * Ec);
    load_tile(sm + TILE_BYTES, g_Bbf + ((size_t)0 * NPADc + m0) * Ec);
    __syncthreads();

    #pragma unroll 1
    for (int h = 0; h < Hc; h++) {
        const int p = h & 1;
        const uint32_t Ab = abase + p * BUF_BYTES;
        const uint32_t Bb = Ab + TILE_BYTES;

        if (h < Hc - 1) {
            const int q = 1 - p;
            load_tile(sm + q * BUF_BYTES,
                      g_Abf + ((size_t)(h + 1) * NPADc + n0) * Ec);
            load_tile(sm + q * BUF_BYTES + TILE_BYTES,
                      g_Bbf + ((size_t)(h + 1) * NPADc + m0) * Ec);
        }

        float sim[4][4][4];
        #pragma unroll
        for (int mt = 0; mt < 4; mt++)
            #pragma unroll
            for (int nt = 0; nt < 4; nt++)
                #pragma unroll
                for (int r = 0; r < 4; r++) sim[mt][nt][r] = 0.f;

        #pragma unroll
        for (int k = 0; k < 4; k++) {
            uint32_t afr[4][4];
            #pragma unroll
            for (int mt = 0; mt < 4; mt++) {
                uint32_t off = (uint32_t)(a_row + mt * 16) * 128 + (k * 2 + a_sh) * 16;
                uint32_t sw = off ^ ((off >> 3) & 0x70);
                ldsm_x4(afr[mt], Ab + sw);
            }
            uint32_t bfr[4][2];
            #pragma unroll
            for (int nt = 0; nt < 4; nt++) {
                uint32_t off = (uint32_t)(b_row + nt * 8) * 128 + (k * 2 + b_sh) * 16;
                uint32_t sw = off ^ ((off >> 3) & 0x70);
                ldsm_x2(bfr[nt], Bb + sw);
            }
            #pragma unroll
            for (int mt = 0; mt < 4; mt++)
                #pragma unroll
                for (int nt = 0; nt < 4; nt++)
                    mma_bf16(sim[mt][nt], afr[mt], bfr[nt]);
        }

        #pragma unroll
        for (int mt = 0; mt < 4; mt++)
            #pragma unroll
            for (int nt = 0; nt < 4; nt++) {
                #pragma unroll
                for (int half = 0; half < 2; half++) {
                    uint64_t x = pk2(sim[mt][nt][half * 2],
                                     sim[mt][nt][half * 2 + 1]);
                    uint64_t u = f2mul(x, x);
                    uint64_t pp = f2fma(u, C9, C7);
                    pp = f2fma(u, pp, C5);
                    pp = f2fma(u, pp, C3);
                    pp = f2fma(u, pp, C1);
                    acc2[mt][nt][half] =
                        f2add(acc2[mt][nt][half], f2fma(x, pp, HALF));
                }
            }

        __syncthreads();
    }

    const uint64_t SCALE = pk2(0.125f, 0.125f);
    const int g = lane >> 2;
    const int tig = lane & 3;
    #pragma unroll
    for (int mt = 0; mt < 4; mt++) {
        int gn0 = n0 + wm * 64 + mt * 16 + g;
        #pragma unroll
        for (int nt = 0; nt < 4; nt++) {
            int gm = m0 + wn * 32 + nt * 8 + tig * 2;
            if (gm < NNc) {
                if (gn0 < NNc) {
                    uint64_t v = f2mul(acc2[mt][nt][0], SCALE);
                    *(uint64_t*)&adj[(size_t)gn0 * NNc + gm] = v;
                }
                if (gn0 + 8 < NNc) {
                    uint64_t v = f2mul(acc2[mt][nt][1], SCALE);
                    *(uint64_t*)&adj[(size_t)(gn0 + 8) * NNc + gm] = v;
                }
            }
        }
    }
}

// =====================================================================
// launch: fork-join across 3 streams so independent branches run
// concurrently inside the captured graph.
//   main:  embed -> adj                    (critical path)
//   s1:    fill_teacher ------+
//   s2:    sq -> xt -> d2 ----+--> topk
// =====================================================================
extern "C" void kernel_launch(void* const* d_in, const int* in_sizes, int n_in,
                              void* d_out, int out_size) {
    (void)in_sizes; (void)n_in; (void)out_size;
    const float* lm_X     = (const float*)d_in[0];
    const float* lm_Y     = (const float*)d_in[1];
    const float* tg_X     = (const float*)d_in[2];
    const float* lm_delay = (const float*)d_in[4];
    const float* tg_delay = (const float*)d_in[5];
    const float* W_emb    = (const float*)d_in[6];
    const float* b_emb    = (const float*)d_in[7];
    const float* w1       = (const float*)d_in[8];
    const float* w2       = (const float*)d_in[9];

    float* out     = (float*)d_out;
    float* y_pred  = out;                       // [2000, 2]
    float* adj     = out + 4000;                // [4000, 4000]
    float* teacher = adj + (size_t)NNc * NNc;   // [4000, 4000]

    static bool init = false;
    static cudaStream_t s1, s2;
    static cudaEvent_t ef, e_fill, e_join;
    const int ADJ_SMEM = 2 * BUF_BYTES + 1024;  // 66560
    if (!init) {
        cudaFuncSetAttribute(adj_mm_kernel,
                             cudaFuncAttributeMaxDynamicSharedMemorySize, ADJ_SMEM);
        cudaStreamCreateWithFlags(&s1, cudaStreamNonBlocking);
        cudaStreamCreateWithFlags(&s2, cudaStreamNonBlocking);
        cudaEventCreateWithFlags(&ef,     cudaEventDisableTiming);
        cudaEventCreateWithFlags(&e_fill, cudaEventDisableTiming);
        cudaEventCreateWithFlags(&e_join, cudaEventDisableTiming);
        init = true;
    }

    // fork
    cudaEventRecord(ef, 0);
    cudaStreamWaitEvent(s1, ef, 0);
    cudaStreamWaitEvent(s2, ef, 0);

    // branch s1: teacher base fill
    fill_teacher_kernel<<<dim3(4, NNc), 256, 0, s1>>>(teacher);
    cudaEventRecord(e_fill, s1);

    // branch s2: knn pipeline
    sq_kernel<<<8, 256, 0, s2>>>(lm_X);
    xt_kernel<<<(Ec * MPADc + 255) / 256, 256, 0, s2>>>(lm_X);
    d2_kernel<<<528, 256, 0, s2>>>();
    cudaStreamWaitEvent(s2, e_fill, 0);
    topk_kernel<<<N1c, 256, 0, s2>>>(lm_Y, y_pred, teacher);
    cudaEventRecord(e_join, s2);

    // main branch: embedding -> big adjacency GEMM
    embed_kernel<<<512, 256>>>(lm_X, tg_X, lm_delay, tg_delay,
                               W_emb, b_emb, w1, w2);
    adj_mm_kernel<<<dim3(32, 32), 256, ADJ_SMEM>>>(adj);

    // join
    cudaStreamWaitEvent(0, e_join, 0);
}

// round 6
// speedup vs baseline: 5.3405x; 1.1065x over previous
#include <cuda_runtime.h>
#include <cuda_bf16.h>
#include <cstdint>

// Problem constants (fixed instance)
#define N1c 2000     // landmarks
#define NNc 4000     // total nodes
#define NPADc 4096   // padded node count
#define Dc 63        // feature dim
#define Ec 64        // embedding dim
#define Hc 8         // heads
#define KNNc 5
#define MPADc 2048   // padded col count for d2 matrix

// -------- device scratch (no allocations allowed) --------
__device__ __nv_bfloat16 g_Abf[(size_t)Hc * NPADc * Ec];  // [h][n][e] normalized a (bf16)
__device__ __nv_bfloat16 g_Bbf[(size_t)Hc * NPADc * Ec];  // [h][n][e] normalized b (bf16)
__device__ float g_sq[N1c];                               // row squared norms of lm_X
__device__ float g_XT[Ec * MPADc];                        // lm_X transposed [64][2048]
__device__ float g_d2[(size_t)N1c * MPADc];               // pairwise squared distances

__device__ __forceinline__ uint32_t smem_u32(const void* p) {
    uint32_t a;
    asm("{ .reg .u64 t; cvta.to.shared.u64 t, %1; cvt.u32.u64 %0, t; }"
        : "=r"(a) : "l"(p));
    return a;
}

// -------- packed f32x2 helpers --------
__device__ __forceinline__ uint64_t pk2(float lo, float hi) {
    uint64_t r;
    asm("mov.b64 %0, {%1, %2};" : "=l"(r) : "f"(lo), "f"(hi));
    return r;
}
__device__ __forceinline__ uint64_t f2mul(uint64_t a, uint64_t b) {
    uint64_t d;
    asm("mul.rn.f32x2 %0, %1, %2;" : "=l"(d) : "l"(a), "l"(b));
    return d;
}
__device__ __forceinline__ uint64_t f2fma(uint64_t a, uint64_t b, uint64_t c) {
    uint64_t d;
    asm("fma.rn.f32x2 %0, %1, %2, %3;" : "=l"(d) : "l"(a), "l"(b), "l"(c));
    return d;
}
__device__ __forceinline__ uint64_t f2add(uint64_t a, uint64_t b) {
    uint64_t d;
    asm("add.rn.f32x2 %0, %1, %2;" : "=l"(d) : "l"(a), "l"(b));
    return d;
}

// -------- cp.async helpers --------
__device__ __forceinline__ void cp16(uint32_t s_dst, const void* g_src) {
    asm volatile("cp.async.cg.shared.global [%0], [%1], 16;"
                 :: "r"(s_dst), "l"(g_src));
}
__device__ __forceinline__ void cp_commit() {
    asm volatile("cp.async.commit_group;");
}
template <int N>
__device__ __forceinline__ void cp_wait() {
    asm volatile("cp.async.wait_group %0;" :: "n"(N));
}

// =====================================================================
// teacher adjacency fill
// =====================================================================
__global__ void fill_teacher_kernel(float* __restrict__ t) {
    int j = (blockIdx.x * 256 + threadIdx.x) * 4;
    int i = blockIdx.y;
    if (j < NNc) {
        float v = ((i < N1c) != (j < N1c)) ? 1.0f : 0.0f;
        *(float4*)&t[(size_t)i * NNc + j] = make_float4(v, v, v, v);
    }
}

// =====================================================================
// squared norms of landmark rows
// =====================================================================
__global__ void sq_kernel(const float* __restrict__ lm_X) {
    int n = blockIdx.x * blockDim.x + threadIdx.x;
    if (n < N1c) {
        float s = 0.f;
        #pragma unroll
        for (int k = 0; k < Dc; k++) {
            float x = lm_X[n * Dc + k];
            s = fmaf(x, x, s);
        }
        g_sq[n] = s;
    }
}

// =====================================================================
// transpose lm_X -> g_XT [64][2048]
// =====================================================================
__global__ void xt_kernel(const float* __restrict__ lm_X) {
    int idx = blockIdx.x * 256 + threadIdx.x;
    if (idx < Ec * MPADc) {
        int k = idx / MPADc;
        int n = idx % MPADc;
        g_XT[idx] = (k < Dc && n < N1c) ? lm_X[n * Dc + k] : 0.f;
    }
}

// =====================================================================
// embedding + per-head normalized vectors (R5 version)
// =====================================================================
__global__ void __launch_bounds__(256) embed_kernel(
        const float* __restrict__ lm_X,
        const float* __restrict__ tg_X,
        const float* __restrict__ lm_delay,
        const float* __restrict__ tg_delay,
        const float* __restrict__ W_emb,
        const float* __restrict__ b_emb,
        const float* __restrict__ w1,
        const float* __restrict__ w2) {
    __shared__ float Wsh[Ec * 65];
    __shared__ float w1T[Hc * Ec];
    __shared__ float w2T[Hc * Ec];
    __shared__ float feat[8][Ec];

    const int tid = threadIdx.x;
    const int lane = tid & 31;
    const int wp = tid >> 5;
    const int n = blockIdx.x * 8 + wp;

    for (int idx = tid; idx < Ec * Ec; idx += 256)
        Wsh[(idx >> 6) * 65 + (idx & 63)] = W_emb[idx];
    for (int idx = tid; idx < Hc * Ec; idx += 256) {
        int h = idx & 7, j = idx >> 3;
        w1T[h * Ec + j] = w1[idx];
        w2T[h * Ec + j] = w2[idx];
    }

    const bool pad = (n >= NNc);
    if (!pad) {
        const float* src = (n < N1c) ? lm_X + (size_t)n * Dc
                                     : tg_X + (size_t)(n - N1c) * Dc;
        float dly = (n < N1c) ? lm_delay[n] : tg_delay[n - N1c];
        feat[wp][lane] = src[lane];
        feat[wp][lane + 32] = (lane < 31) ? src[lane + 32] : dly;
    }
    __syncthreads();

    if (pad) {
        const __nv_bfloat162 z = __floats2bfloat162_rn(0.f, 0.f);
        #pragma unroll
        for (int h = 0; h < Hc; h++) {
            *(__nv_bfloat162*)&g_Abf[((size_t)h * NPADc + n) * Ec + 2 * lane] = z;
            *(__nv_bfloat162*)&g_Bbf[((size_t)h * NPADc + n) * Ec + 2 * lane] = z;
        }
        return;
    }

    const int j0 = 2 * lane, j1 = 2 * lane + 1;
    float e0 = b_emb[j0], e1 = b_emb[j1];
    const float* W0 = &Wsh[j0 * 65];
    const float* W1 = &Wsh[j1 * 65];
    #pragma unroll
    for (int k = 0; k < Ec; k++) {
        float f = feat[wp][k];
        e0 = fmaf(W0[k], f, e0);
        e1 = fmaf(W1[k], f, e1);
    }

    float a0[Hc], a1[Hc], b0[Hc], b1[Hc], va[Hc], vb[Hc];
    #pragma unroll
    for (int h = 0; h < Hc; h++) {
        float2 wa = *(const float2*)&w1T[h * Ec + j0];
        float2 wb = *(const float2*)&w2T[h * Ec + j0];
        a0[h] = e0 * wa.x; a1[h] = e1 * wa.y;
        b0[h] = e0 * wb.x; b1[h] = e1 * wb.y;
        va[h] = fmaf(a0[h], a0[h], a1[h] * a1[h]);
        vb[h] = fmaf(b0[h], b0[h], b1[h] * b1[h]);
    }
    #pragma unroll
    for (int o = 16; o > 0; o >>= 1) {
        #pragma unroll
        for (int h = 0; h < Hc; h++) {
            va[h] += __shfl_xor_sync(0xffffffffu, va[h], o);
            vb[h] += __shfl_xor_sync(0xffffffffu, vb[h], o);
        }
    }
    #pragma unroll
    for (int h = 0; h < Hc; h++) {
        float ra = rsqrtf(va[h]);
        float rb = rsqrtf(vb[h]);
        *(__nv_bfloat162*)&g_Abf[((size_t)h * NPADc + n) * Ec + j0] =
            __floats2bfloat162_rn(a0[h] * ra, a1[h] * ra);
        *(__nv_bfloat162*)&g_Bbf[((size_t)h * NPADc + n) * Ec + j0] =
            __floats2bfloat162_rn(b0[h] * rb, b1[h] * rb);
    }
}

// =====================================================================
// d2 GEMM, symmetric upper-tri tiles
// =====================================================================
__global__ void __launch_bounds__(256) d2_kernel() {
    __shared__ float As[Ec][64];
    __shared__ float Bs[Ec][65];

    const int tid = threadIdx.x;
    const int tx = tid >> 4, ty = tid & 15;

    int bid = blockIdx.x;
    int bx = (int)((sqrtf(8.f * (float)bid + 1.f) - 1.f) * 0.5f);
    while ((bx + 1) * (bx + 2) / 2 <= bid) bx++;
    while (bx * (bx + 1) / 2 > bid) bx--;
    int by = bid - bx * (bx + 1) / 2;

    const int n0 = by * 64;
    const int m0 = bx * 64;

    #pragma unroll
    for (int p = 0; p < 16; p++) {
        int idx = p * 256 + tid;
        int k = idx >> 6, r = idx & 63;
        As[k][r] = g_XT[k * MPADc + n0 + r];
        Bs[k][r] = g_XT[k * MPADc + m0 + r];
    }
    __syncthreads();

    float dot[4][4];
    #pragma unroll
    for (int i = 0; i < 4; i++)
        #pragma unroll
        for (int j = 0; j < 4; j++) dot[i][j] = 0.f;

    #pragma unroll 16
    for (int k = 0; k < Ec; k++) {
        float a[4], b[4];
        #pragma unroll
        for (int i = 0; i < 4; i++) a[i] = As[k][tx * 4 + i];
        #pragma unroll
        for (int j = 0; j < 4; j++) b[j] = Bs[k][ty * 4 + j];
        #pragma unroll
        for (int i = 0; i < 4; i++)
            #pragma unroll
            for (int j = 0; j < 4; j++)
                dot[i][j] = fmaf(a[i], b[j], dot[i][j]);
    }

    const float INF = __int_as_float(0x7f800000);
    float v[4][4];
    #pragma unroll
    for (int i = 0; i < 4; i++) {
        int nn = n0 + tx * 4 + i;
        float sqn = (nn < N1c) ? g_sq[nn] : 0.f;
        #pragma unroll
        for (int j = 0; j < 4; j++) {
            int mm = m0 + ty * 4 + j;
            float val = INF;
            if (nn < N1c && mm < N1c && mm != nn)
                val = fmaxf(sqn + g_sq[mm] - 2.f * dot[i][j], 0.f);
            v[i][j] = val;
        }
    }

    #pragma unroll
    for (int i = 0; i < 4; i++) {
        int nn = n0 + tx * 4 + i;
        if (nn < N1c)
            *(float4*)&g_d2[(size_t)nn * MPADc + m0 + ty * 4] =
                make_float4(v[i][0], v[i][1], v[i][2], v[i][3]);
    }

    if (bx == by) return;

    __syncthreads();
    #pragma unroll
    for (int i = 0; i < 4; i++)
        #pragma unroll
        for (int j = 0; j < 4; j++)
            Bs[tx * 4 + i][ty * 4 + j] = v[i][j];
    __syncthreads();

    #pragma unroll
    for (int i = 0; i < 4; i++) {
        int mm = m0 + tx * 4 + i;
        if (mm < N1c) {
            float4 o;
            o.x = Bs[ty * 4 + 0][tx * 4 + i];
            o.y = Bs[ty * 4 + 1][tx * 4 + i];
            o.z = Bs[ty * 4 + 2][tx * 4 + i];
            o.w = Bs[ty * 4 + 3][tx * 4 + i];
            *(float4*)&g_d2[(size_t)mm * MPADc + n0 + ty * 4] = o;
        }
    }
}

// =====================================================================
// top-5 per row from d2; y_pred + teacher scatter
// =====================================================================
__global__ void topk_kernel(const float* __restrict__ lm_Y,
                            float* __restrict__ y_pred,
                            float* __restrict__ teacher) {
    __shared__ unsigned long long wmin[8];
    __shared__ unsigned long long swin;
    const int n = blockIdx.x;
    const int tid = threadIdx.x;
    const int lane = tid & 31;
    const int wp = tid >> 5;
    const float INF = __int_as_float(0x7f800000);

    float bd[KNNc];
    int   bi[KNNc];
    #pragma unroll
    for (int t = 0; t < KNNc; t++) { bd[t] = INF; bi[t] = 0; }

    #pragma unroll
    for (int it = 0; it < 8; it++) {
        int m = it * 256 + tid;
        float d2 = g_d2[(size_t)n * MPADc + m];
        if (d2 < bd[KNNc - 1]) {
            bd[KNNc - 1] = d2; bi[KNNc - 1] = m;
            #pragma unroll
            for (int t = KNNc - 1; t > 0; t--) {
                if (bd[t] < bd[t - 1]) {
                    float td = bd[t]; bd[t] = bd[t - 1]; bd[t - 1] = td;
                    int   ti = bi[t]; bi[t] = bi[t - 1]; bi[t - 1] = ti;
                }
            }
        }
    }

    float y0 = 0.f, y1 = 0.f;
    #pragma unroll 1
    for (int r = 0; r < KNNc; r++) {
        unsigned long long key =
            (((unsigned long long)__float_as_uint(bd[0])) << 32) | (unsigned)bi[0];
        unsigned long long wk = key;
        #pragma unroll
        for (int o = 16; o > 0; o >>= 1) {
            unsigned long long t = __shfl_xor_sync(0xffffffffu, wk, o);
            if (t < wk) wk = t;
        }
        if (lane == 0) wmin[wp] = wk;
        __syncthreads();
        if (tid == 0) {
            unsigned long long m = wmin[0];
            #pragma unroll
            for (int i = 1; i < 8; i++) if (wmin[i] < m) m = wmin[i];
            swin = m;
        }
        __syncthreads();
        unsigned long long win = swin;
        int wm = (int)(win & 0xffffffffull);
        if (key == win) {
            #pragma unroll
            for (int t = 0; t < KNNc - 1; t++) { bd[t] = bd[t + 1]; bi[t] = bi[t + 1]; }
            bd[KNNc - 1] = INF; bi[KNNc - 1] = 0;
        }
        if (tid == 0) {
            teacher[(size_t)n * NNc + wm] = 1.0f;
            y0 += lm_Y[wm * 2 + 0];
            y1 += lm_Y[wm * 2 + 1];
        }
    }
    if (tid == 0) {
        y_pred[n * 2 + 0] = y0 * 0.2f;
        y_pred[n * 2 + 1] = y1 * 0.2f;
    }
}

// =====================================================================
// HMMA adjacency kernel v2: 128x128 tile, 512 threads, 4x4 warp grid,
// warp tile 32x32; cp.async double-buffered head pipeline.
// =====================================================================
#define A_BYTES 16384               // 128 rows x 128B
#define STAGE_BYTES (2 * A_BYTES)   // A + B

__device__ __forceinline__ void ldsm_x4(uint32_t* r, uint32_t addr) {
    asm volatile("ldmatrix.sync.aligned.m8n8.x4.shared.b16 {%0,%1,%2,%3}, [%4];"
                 : "=r"(r[0]), "=r"(r[1]), "=r"(r[2]), "=r"(r[3]) : "r"(addr));
}
__device__ __forceinline__ void ldsm_x2(uint32_t* r, uint32_t addr) {
    asm volatile("ldmatrix.sync.aligned.m8n8.x2.shared.b16 {%0,%1}, [%2];"
                 : "=r"(r[0]), "=r"(r[1]) : "r"(addr));
}
__device__ __forceinline__ void mma_bf16(float* c, const uint32_t* a,
                                         const uint32_t* b) {
    asm volatile(
        "mma.sync.aligned.m16n8k16.row.col.f32.bf16.bf16.f32 "
        "{%0,%1,%2,%3}, {%4,%5,%6,%7}, {%8,%9}, {%0,%1,%2,%3};"
        : "+f"(c[0]), "+f"(c[1]), "+f"(c[2]), "+f"(c[3])
        : "r"(a[0]), "r"(a[1]), "r"(a[2]), "r"(a[3]), "r"(b[0]), "r"(b[1]));
}

__global__ void __launch_bounds__(512, 1) adj_mm_kernel(float* __restrict__ adj) {
    extern __shared__ char dsm[];
    uint32_t dbase = smem_u32(dsm);
    uint32_t abase = (dbase + 1023u) & ~1023u;

    const int tid = threadIdx.x;
    const int lane = tid & 31;
    const int wid = tid >> 5;
    const int wm = wid & 3;    // 4 warp-rows of 32
    const int wn = wid >> 2;   // 4 warp-cols of 32
    const int n0 = blockIdx.y * 128;
    const int m0 = blockIdx.x * 128;

    // async tile pair load: A rows from g_Abf[n0..], B rows from g_Bbf[m0..]
    auto load_stage = [&](uint32_t sbase, int h) {
        const char* asrc = (const char*)(g_Abf + ((size_t)h * NPADc + n0) * Ec);
        const char* bsrc = (const char*)(g_Bbf + ((size_t)h * NPADc + m0) * Ec);
        // 1024 chunks each, 512 threads -> 2 chunks per tile per thread
        #pragma unroll
        for (int i = 0; i < 2; i++) {
            int c = tid + i * 512;
            int r = c >> 3, s = c & 7;
            uint32_t off = (uint32_t)r * 128 + s * 16;
            uint32_t sw = off ^ ((off >> 3) & 0x70);
            cp16(sbase + sw, asrc + (size_t)r * 128 + s * 16);
            cp16(sbase + A_BYTES + sw, bsrc + (size_t)r * 128 + s * 16);
        }
        cp_commit();
    };

    const int a_row = wm * 32 + (lane & 15);   // + mt*16
    const int a_sh  = lane >> 4;
    const int b_row = wn * 32 + (lane & 7);    // + nt*8
    const int b_sh  = (lane >> 3) & 1;

    const uint64_t C9 = pk2(2.1356922e-5f, 2.1356922e-5f);
    const uint64_t C7 = pk2(-2.1081349e-4f, -2.1081349e-4f);
    const uint64_t C5 = pk2(2.0833333e-3f, 2.0833333e-3f);
    const uint64_t C3 = pk2(-2.0833334e-2f, -2.0833334e-2f);
    const uint64_t C1 = pk2(0.25f, 0.25f);
    const uint64_t HALF = pk2(0.5f, 0.5f);

    uint64_t acc2[2][4][2];
    #pragma unroll
    for (int mt = 0; mt < 2; mt++)
        #pragma unroll
        for (int nt = 0; nt < 4; nt++) {
            acc2[mt][nt][0] = 0ull;
            acc2[mt][nt][1] = 0ull;
        }

    load_stage(abase, 0);

    #pragma unroll 1
    for (int h = 0; h < Hc; h++) {
        const int p = h & 1;
        if (h < Hc - 1) {
            load_stage(abase + (1 - p) * STAGE_BYTES, h + 1);
            cp_wait<1>();
        } else {
            cp_wait<0>();
        }
        __syncthreads();

        const uint32_t Ab = abase + p * STAGE_BYTES;
        const uint32_t Bb = Ab + A_BYTES;

        float sim[2][4][4];
        #pragma unroll
        for (int mt = 0; mt < 2; mt++)
            #pragma unroll
            for (int nt = 0; nt < 4; nt++)
                #pragma unroll
                for (int r = 0; r < 4; r++) sim[mt][nt][r] = 0.f;

        #pragma unroll
        for (int k = 0; k < 4; k++) {
            uint32_t afr[2][4];
            #pragma unroll
            for (int mt = 0; mt < 2; mt++) {
                uint32_t off = (uint32_t)(a_row + mt * 16) * 128 + (k * 2 + a_sh) * 16;
                uint32_t sw = off ^ ((off >> 3) & 0x70);
                ldsm_x4(afr[mt], Ab + sw);
            }
            uint32_t bfr[4][2];
            #pragma unroll
            for (int nt = 0; nt < 4; nt++) {
                uint32_t off = (uint32_t)(b_row + nt * 8) * 128 + (k * 2 + b_sh) * 16;
                uint32_t sw = off ^ ((off >> 3) & 0x70);
                ldsm_x2(bfr[nt], Bb + sw);
            }
            #pragma unroll
            for (int mt = 0; mt < 2; mt++)
                #pragma unroll
                for (int nt = 0; nt < 4; nt++)
                    mma_bf16(sim[mt][nt], afr[mt], bfr[nt]);
        }

        #pragma unroll
        for (int mt = 0; mt < 2; mt++)
            #pragma unroll
            for (int nt = 0; nt < 4; nt++) {
                #pragma unroll
                for (int half = 0; half < 2; half++) {
                    uint64_t x = pk2(sim[mt][nt][half * 2],
                                     sim[mt][nt][half * 2 + 1]);
                    uint64_t u = f2mul(x, x);
                    uint64_t pp = f2fma(u, C9, C7);
                    pp = f2fma(u, pp, C5);
                    pp = f2fma(u, pp, C3);
                    pp = f2fma(u, pp, C1);
                    acc2[mt][nt][half] =
                        f2add(acc2[mt][nt][half], f2fma(x, pp, HALF));
                }
            }

        __syncthreads();   // all warps done with buffer p before it is refilled
    }

    const uint64_t SCALE = pk2(0.125f, 0.125f);
    const int g = lane >> 2;
    const int tig = lane & 3;
    #pragma unroll
    for (int mt = 0; mt < 2; mt++) {
        int gn0 = n0 + wm * 32 + mt * 16 + g;
        #pragma unroll
        for (int nt = 0; nt < 4; nt++) {
            int gm = m0 + wn * 32 + nt * 8 + tig * 2;
            if (gm < NNc) {
                if (gn0 < NNc) {
                    uint64_t v = f2mul(acc2[mt][nt][0], SCALE);
                    *(uint64_t*)&adj[(size_t)gn0 * NNc + gm] = v;
                }
                if (gn0 + 8 < NNc) {
                    uint64_t v = f2mul(acc2[mt][nt][1], SCALE);
                    *(uint64_t*)&adj[(size_t)(gn0 + 8) * NNc + gm] = v;
                }
            }
        }
    }
}

// =====================================================================
// launch: fork-join across 3 streams
// =====================================================================
extern "C" void kernel_launch(void* const* d_in, const int* in_sizes, int n_in,
                              void* d_out, int out_size) {
    (void)in_sizes; (void)n_in; (void)out_size;
    const float* lm_X     = (const float*)d_in[0];
    const float* lm_Y     = (const float*)d_in[1];
    const float* tg_X     = (const float*)d_in[2];
    const float* lm_delay = (const float*)d_in[4];
    const float* tg_delay = (const float*)d_in[5];
    const float* W_emb    = (const float*)d_in[6];
    const float* b_emb    = (const float*)d_in[7];
    const float* w1       = (const float*)d_in[8];
    const float* w2       = (const float*)d_in[9];

    float* out     = (float*)d_out;
    float* y_pred  = out;                       // [2000, 2]
    float* adj     = out + 4000;                // [4000, 4000]
    float* teacher = adj + (size_t)NNc * NNc;   // [4000, 4000]

    static bool init = false;
    static cudaStream_t s1, s2;
    static cudaEvent_t ef, e_fill, e_join;
    const int ADJ_SMEM = 2 * STAGE_BYTES + 1024;  // 66560
    if (!init) {
        cudaFuncSetAttribute(adj_mm_kernel,
                             cudaFuncAttributeMaxDynamicSharedMemorySize, ADJ_SMEM);
        cudaStreamCreateWithFlags(&s1, cudaStreamNonBlocking);
        cudaStreamCreateWithFlags(&s2, cudaStreamNonBlocking);
        cudaEventCreateWithFlags(&ef,     cudaEventDisableTiming);
        cudaEventCreateWithFlags(&e_fill, cudaEventDisableTiming);
        cudaEventCreateWithFlags(&e_join, cudaEventDisableTiming);
        init = true;
    }

    // fork
    cudaEventRecord(ef, 0);
    cudaStreamWaitEvent(s1, ef, 0);
    cudaStreamWaitEvent(s2, ef, 0);

    // branch s1: teacher base fill
    fill_teacher_kernel<<<dim3(4, NNc), 256, 0, s1>>>(teacher);
    cudaEventRecord(e_fill, s1);

    // branch s2: knn pipeline
    sq_kernel<<<8, 256, 0, s2>>>(lm_X);
    xt_kernel<<<(Ec * MPADc + 255) / 256, 256, 0, s2>>>(lm_X);
    d2_kernel<<<528, 256, 0, s2>>>();
    cudaStreamWaitEvent(s2, e_fill, 0);
    topk_kernel<<<N1c, 256, 0, s2>>>(lm_Y, y_pred, teacher);
    cudaEventRecord(e_join, s2);

    // main branch: embedding -> big adjacency GEMM
    embed_kernel<<<512, 256>>>(lm_X, tg_X, lm_delay, tg_delay,
                               W_emb, b_emb, w1, w2);
    adj_mm_kernel<<<dim3(32, 32), 512, ADJ_SMEM>>>(adj);

    // join
    cudaStreamWaitEvent(0, e_join, 0);
}

// round 7
// speedup vs baseline: 5.3431x; 1.0005x over previous
#include <cuda_runtime.h>
#include <cuda_bf16.h>
#include <cstdint>

// Problem constants (fixed instance)
#define N1c 2000     // landmarks
#define NNc 4000     // total nodes
#define NPADc 4096   // padded node count
#define Dc 63        // feature dim
#define Ec 64        // embedding dim
#define Hc 8         // heads
#define KNNc 5
#define MPADc 2048   // padded col count for d2 matrix

// -------- device scratch (no allocations allowed) --------
__device__ __nv_bfloat16 g_Abf[(size_t)Hc * NPADc * Ec];  // [h][n][e] normalized a (bf16)
__device__ __nv_bfloat16 g_Bbf[(size_t)Hc * NPADc * Ec];  // [h][n][e] normalized b (bf16)
__device__ float g_sq[N1c];                               // row squared norms of lm_X
__device__ float g_XT[Ec * MPADc];                        // lm_X transposed [64][2048]
__device__ float g_d2[(size_t)N1c * MPADc];               // pairwise squared distances

__device__ __forceinline__ uint32_t smem_u32(const void* p) {
    uint32_t a;
    asm("{ .reg .u64 t; cvta.to.shared.u64 t, %1; cvt.u32.u64 %0, t; }"
        : "=r"(a) : "l"(p));
    return a;
}

// -------- cp.async helpers --------
__device__ __forceinline__ void cp16(uint32_t s_dst, const void* g_src) {
    asm volatile("cp.async.cg.shared.global [%0], [%1], 16;"
                 :: "r"(s_dst), "l"(g_src));
}
__device__ __forceinline__ void cp_commit() {
    asm volatile("cp.async.commit_group;");
}
template <int N>
__device__ __forceinline__ void cp_wait() {
    asm volatile("cp.async.wait_group %0;" :: "n"(N));
}

// fast tanh (MUFU.TANH)
__device__ __forceinline__ float tanh_fast(float x) {
    float t;
    asm("tanh.approx.f32 %0, %1;" : "=f"(t) : "f"(x));
    return t;
}

// =====================================================================
// teacher adjacency fill
// =====================================================================
__global__ void fill_teacher_kernel(float* __restrict__ t) {
    int j = (blockIdx.x * 256 + threadIdx.x) * 4;
    int i = blockIdx.y;
    if (j < NNc) {
        float v = ((i < N1c) != (j < N1c)) ? 1.0f : 0.0f;
        *(float4*)&t[(size_t)i * NNc + j] = make_float4(v, v, v, v);
    }
}

// =====================================================================
// squared norms of landmark rows
// =====================================================================
__global__ void sq_kernel(const float* __restrict__ lm_X) {
    int n = blockIdx.x * blockDim.x + threadIdx.x;
    if (n < N1c) {
        float s = 0.f;
        #pragma unroll
        for (int k = 0; k < Dc; k++) {
            float x = lm_X[n * Dc + k];
            s = fmaf(x, x, s);
        }
        g_sq[n] = s;
    }
}

// =====================================================================
// transpose lm_X -> g_XT [64][2048]
// =====================================================================
__global__ void xt_kernel(const float* __restrict__ lm_X) {
    int idx = blockIdx.x * 256 + threadIdx.x;
    if (idx < Ec * MPADc) {
        int k = idx / MPADc;
        int n = idx % MPADc;
        g_XT[idx] = (k < Dc && n < N1c) ? lm_X[n * Dc + k] : 0.f;
    }
}

// =====================================================================
// embedding + per-head normalized vectors
// =====================================================================
__global__ void __launch_bounds__(256) embed_kernel(
        const float* __restrict__ lm_X,
        const float* __restrict__ tg_X,
        const float* __restrict__ lm_delay,
        const float* __restrict__ tg_delay,
        const float* __restrict__ W_emb,
        const float* __restrict__ b_emb,
        const float* __restrict__ w1,
        const float* __restrict__ w2) {
    __shared__ float Wsh[Ec * 65];
    __shared__ float w1T[Hc * Ec];
    __shared__ float w2T[Hc * Ec];
    __shared__ float feat[8][Ec];

    const int tid = threadIdx.x;
    const int lane = tid & 31;
    const int wp = tid >> 5;
    const int n = blockIdx.x * 8 + wp;

    for (int idx = tid; idx < Ec * Ec; idx += 256)
        Wsh[(idx >> 6) * 65 + (idx & 63)] = W_emb[idx];
    for (int idx = tid; idx < Hc * Ec; idx += 256) {
        int h = idx & 7, j = idx >> 3;
        w1T[h * Ec + j] = w1[idx];
        w2T[h * Ec + j] = w2[idx];
    }

    const bool pad = (n >= NNc);
    if (!pad) {
        const float* src = (n < N1c) ? lm_X + (size_t)n * Dc
                                     : tg_X + (size_t)(n - N1c) * Dc;
        float dly = (n < N1c) ? lm_delay[n] : tg_delay[n - N1c];
        feat[wp][lane] = src[lane];
        feat[wp][lane + 32] = (lane < 31) ? src[lane + 32] : dly;
    }
    __syncthreads();

    if (pad) {
        const __nv_bfloat162 z = __floats2bfloat162_rn(0.f, 0.f);
        #pragma unroll
        for (int h = 0; h < Hc; h++) {
            *(__nv_bfloat162*)&g_Abf[((size_t)h * NPADc + n) * Ec + 2 * lane] = z;
            *(__nv_bfloat162*)&g_Bbf[((size_t)h * NPADc + n) * Ec + 2 * lane] = z;
        }
        return;
    }

    const int j0 = 2 * lane, j1 = 2 * lane + 1;
    float e0 = b_emb[j0], e1 = b_emb[j1];
    const float* W0 = &Wsh[j0 * 65];
    const float* W1 = &Wsh[j1 * 65];
    #pragma unroll
    for (int k = 0; k < Ec; k++) {
        float f = feat[wp][k];
        e0 = fmaf(W0[k], f, e0);
        e1 = fmaf(W1[k], f, e1);
    }

    float a0[Hc], a1[Hc], b0[Hc], b1[Hc], va[Hc], vb[Hc];
    #pragma unroll
    for (int h = 0; h < Hc; h++) {
        float2 wa = *(const float2*)&w1T[h * Ec + j0];
        float2 wb = *(const float2*)&w2T[h * Ec + j0];
        a0[h] = e0 * wa.x; a1[h] = e1 * wa.y;
        b0[h] = e0 * wb.x; b1[h] = e1 * wb.y;
        va[h] = fmaf(a0[h], a0[h], a1[h] * a1[h]);
        vb[h] = fmaf(b0[h], b0[h], b1[h] * b1[h]);
    }
    #pragma unroll
    for (int o = 16; o > 0; o >>= 1) {
        #pragma unroll
        for (int h = 0; h < Hc; h++) {
            va[h] += __shfl_xor_sync(0xffffffffu, va[h], o);
            vb[h] += __shfl_xor_sync(0xffffffffu, vb[h], o);
        }
    }
    #pragma unroll
    for (int h = 0; h < Hc; h++) {
        float ra = rsqrtf(va[h]);
        float rb = rsqrtf(vb[h]);
        *(__nv_bfloat162*)&g_Abf[((size_t)h * NPADc + n) * Ec + j0] =
            __floats2bfloat162_rn(a0[h] * ra, a1[h] * ra);
        *(__nv_bfloat162*)&g_Bbf[((size_t)h * NPADc + n) * Ec + j0] =
            __floats2bfloat162_rn(b0[h] * rb, b1[h] * rb);
    }
}

// =====================================================================
// d2 GEMM, symmetric upper-tri tiles
// =====================================================================
__global__ void __launch_bounds__(256) d2_kernel() {
    __shared__ float As[Ec][64];
    __shared__ float Bs[Ec][65];

    const int tid = threadIdx.x;
    const int tx = tid >> 4, ty = tid & 15;

    int bid = blockIdx.x;
    int bx = (int)((sqrtf(8.f * (float)bid + 1.f) - 1.f) * 0.5f);
    while ((bx + 1) * (bx + 2) / 2 <= bid) bx++;
    while (bx * (bx + 1) / 2 > bid) bx--;
    int by = bid - bx * (bx + 1) / 2;

    const int n0 = by * 64;
    const int m0 = bx * 64;

    #pragma unroll
    for (int p = 0; p < 16; p++) {
        int idx = p * 256 + tid;
        int k = idx >> 6, r = idx & 63;
        As[k][r] = g_XT[k * MPADc + n0 + r];
        Bs[k][r] = g_XT[k * MPADc + m0 + r];
    }
    __syncthreads();

    float dot[4][4];
    #pragma unroll
    for (int i = 0; i < 4; i++)
        #pragma unroll
        for (int j = 0; j < 4; j++) dot[i][j] = 0.f;

    #pragma unroll 16
    for (int k = 0; k < Ec; k++) {
        float a[4], b[4];
        #pragma unroll
        for (int i = 0; i < 4; i++) a[i] = As[k][tx * 4 + i];
        #pragma unroll
        for (int j = 0; j < 4; j++) b[j] = Bs[k][ty * 4 + j];
        #pragma unroll
        for (int i = 0; i < 4; i++)
            #pragma unroll
            for (int j = 0; j < 4; j++)
                dot[i][j] = fmaf(a[i], b[j], dot[i][j]);
    }

    const float INF = __int_as_float(0x7f800000);
    float v[4][4];
    #pragma unroll
    for (int i = 0; i < 4; i++) {
        int nn = n0 + tx * 4 + i;
        float sqn = (nn < N1c) ? g_sq[nn] : 0.f;
        #pragma unroll
        for (int j = 0; j < 4; j++) {
            int mm = m0 + ty * 4 + j;
            float val = INF;
            if (nn < N1c && mm < N1c && mm != nn)
                val = fmaxf(sqn + g_sq[mm] - 2.f * dot[i][j], 0.f);
            v[i][j] = val;
        }
    }

    #pragma unroll
    for (int i = 0; i < 4; i++) {
        int nn = n0 + tx * 4 + i;
        if (nn < N1c)
            *(float4*)&g_d2[(size_t)nn * MPADc + m0 + ty * 4] =
                make_float4(v[i][0], v[i][1], v[i][2], v[i][3]);
    }

    if (bx == by) return;

    __syncthreads();
    #pragma unroll
    for (int i = 0; i < 4; i++)
        #pragma unroll
        for (int j = 0; j < 4; j++)
            Bs[tx * 4 + i][ty * 4 + j] = v[i][j];
    __syncthreads();

    #pragma unroll
    for (int i = 0; i < 4; i++) {
        int mm = m0 + tx * 4 + i;
        if (mm < N1c) {
            float4 o;
            o.x = Bs[ty * 4 + 0][tx * 4 + i];
            o.y = Bs[ty * 4 + 1][tx * 4 + i];
            o.z = Bs[ty * 4 + 2][tx * 4 + i];
            o.w = Bs[ty * 4 + 3][tx * 4 + i];
            *(float4*)&g_d2[(size_t)mm * MPADc + n0 + ty * 4] = o;
        }
    }
}

// =====================================================================
// top-5 per row from d2; y_pred + teacher scatter
// =====================================================================
__global__ void topk_kernel(const float* __restrict__ lm_Y,
                            float* __restrict__ y_pred,
                            float* __restrict__ teacher) {
    __shared__ unsigned long long wmin[8];
    __shared__ unsigned long long swin;
    const int n = blockIdx.x;
    const int tid = threadIdx.x;
    const int lane = tid & 31;
    const int wp = tid >> 5;
    const float INF = __int_as_float(0x7f800000);

    float bd[KNNc];
    int   bi[KNNc];
    #pragma unroll
    for (int t = 0; t < KNNc; t++) { bd[t] = INF; bi[t] = 0; }

    #pragma unroll
    for (int it = 0; it < 8; it++) {
        int m = it * 256 + tid;
        float d2 = g_d2[(size_t)n * MPADc + m];
        if (d2 < bd[KNNc - 1]) {
            bd[KNNc - 1] = d2; bi[KNNc - 1] = m;
            #pragma unroll
            for (int t = KNNc - 1; t > 0; t--) {
                if (bd[t] < bd[t - 1]) {
                    float td = bd[t]; bd[t] = bd[t - 1]; bd[t - 1] = td;
                    int   ti = bi[t]; bi[t] = bi[t - 1]; bi[t - 1] = ti;
                }
            }
        }
    }

    float y0 = 0.f, y1 = 0.f;
    #pragma unroll 1
    for (int r = 0; r < KNNc; r++) {
        unsigned long long key =
            (((unsigned long long)__float_as_uint(bd[0])) << 32) | (unsigned)bi[0];
        unsigned long long wk = key;
        #pragma unroll
        for (int o = 16; o > 0; o >>= 1) {
            unsigned long long t = __shfl_xor_sync(0xffffffffu, wk, o);
            if (t < wk) wk = t;
        }
        if (lane == 0) wmin[wp] = wk;
        __syncthreads();
        if (tid == 0) {
            unsigned long long m = wmin[0];
            #pragma unroll
            for (int i = 1; i < 8; i++) if (wmin[i] < m) m = wmin[i];
            swin = m;
        }
        __syncthreads();
        unsigned long long win = swin;
        int wm = (int)(win & 0xffffffffull);
        if (key == win) {
            #pragma unroll
            for (int t = 0; t < KNNc - 1; t++) { bd[t] = bd[t + 1]; bi[t] = bi[t + 1]; }
            bd[KNNc - 1] = INF; bi[KNNc - 1] = 0;
        }
        if (tid == 0) {
            teacher[(size_t)n * NNc + wm] = 1.0f;
            y0 += lm_Y[wm * 2 + 0];
            y1 += lm_Y[wm * 2 + 1];
        }
    }
    if (tid == 0) {
        y_pred[n * 2 + 0] = y0 * 0.2f;
        y_pred[n * 2 + 1] = y1 * 0.2f;
    }
}

// =====================================================================
// HMMA adjacency kernel v3: 128x128 tile, 512 threads, 4x4 warp grid,
// warp tile 32x32, cp.async double-buffered heads.
// Sigmoid via MUFU: sigma(x) = 0.5 + 0.5*tanh(x/2); accumulate 0.5*t,
// fold the constant 0.5 into the epilogue (out = acc/8 + 0.5).
// =====================================================================
#define A_BYTES 16384               // 128 rows x 128B
#define STAGE_BYTES (2 * A_BYTES)   // A + B

__device__ __forceinline__ void ldsm_x4(uint32_t* r, uint32_t addr) {
    asm volatile("ldmatrix.sync.aligned.m8n8.x4.shared.b16 {%0,%1,%2,%3}, [%4];"
                 : "=r"(r[0]), "=r"(r[1]), "=r"(r[2]), "=r"(r[3]) : "r"(addr));
}
__device__ __forceinline__ void ldsm_x2(uint32_t* r, uint32_t addr) {
    asm volatile("ldmatrix.sync.aligned.m8n8.x2.shared.b16 {%0,%1}, [%2];"
                 : "=r"(r[0]), "=r"(r[1]) : "r"(addr));
}
__device__ __forceinline__ void mma_bf16(float* c, const uint32_t* a,
                                         const uint32_t* b) {
    asm volatile(
        "mma.sync.aligned.m16n8k16.row.col.f32.bf16.bf16.f32 "
        "{%0,%1,%2,%3}, {%4,%5,%6,%7}, {%8,%9}, {%0,%1,%2,%3};"
        : "+f"(c[0]), "+f"(c[1]), "+f"(c[2]), "+f"(c[3])
        : "r"(a[0]), "r"(a[1]), "r"(a[2]), "r"(a[3]), "r"(b[0]), "r"(b[1]));
}

__global__ void __launch_bounds__(512, 1) adj_mm_kernel(float* __restrict__ adj) {
    extern __shared__ char dsm[];
    uint32_t dbase = smem_u32(dsm);
    uint32_t abase = (dbase + 1023u) & ~1023u;

    const int tid = threadIdx.x;
    const int lane = tid & 31;
    const int wid = tid >> 5;
    const int wm = wid & 3;    // 4 warp-rows of 32
    const int wn = wid >> 2;   // 4 warp-cols of 32
    const int n0 = blockIdx.y * 128;
    const int m0 = blockIdx.x * 128;

    auto load_stage = [&](uint32_t sbase, int h) {
        const char* asrc = (const char*)(g_Abf + ((size_t)h * NPADc + n0) * Ec);
        const char* bsrc = (const char*)(g_Bbf + ((size_t)h * NPADc + m0) * Ec);
        #pragma unroll
        for (int i = 0; i < 2; i++) {
            int c = tid + i * 512;
            int r = c >> 3, s = c & 7;
            uint32_t off = (uint32_t)r * 128 + s * 16;
            uint32_t sw = off ^ ((off >> 3) & 0x70);
            cp16(sbase + sw, asrc + (size_t)r * 128 + s * 16);
            cp16(sbase + A_BYTES + sw, bsrc + (size_t)r * 128 + s * 16);
        }
        cp_commit();
    };

    const int a_row = wm * 32 + (lane & 15);
    const int a_sh  = lane >> 4;
    const int b_row = wn * 32 + (lane & 7);
    const int b_sh  = (lane >> 3) & 1;

    float acc[2][4][4];
    #pragma unroll
    for (int mt = 0; mt < 2; mt++)
        #pragma unroll
        for (int nt = 0; nt < 4; nt++)
            #pragma unroll
            for (int r = 0; r < 4; r++) acc[mt][nt][r] = 0.f;

    load_stage(abase, 0);

    #pragma unroll 1
    for (int h = 0; h < Hc; h++) {
        const int p = h & 1;
        if (h < Hc - 1) {
            load_stage(abase + (1 - p) * STAGE_BYTES, h + 1);
            cp_wait<1>();
        } else {
            cp_wait<0>();
        }
        __syncthreads();

        const uint32_t Ab = abase + p * STAGE_BYTES;
        const uint32_t Bb = Ab + A_BYTES;

        float sim[2][4][4];
        #pragma unroll
        for (int mt = 0; mt < 2; mt++)
            #pragma unroll
            for (int nt = 0; nt < 4; nt++)
                #pragma unroll
                for (int r = 0; r < 4; r++) sim[mt][nt][r] = 0.f;

        #pragma unroll
        for (int k = 0; k < 4; k++) {
            uint32_t afr[2][4];
            #pragma unroll
            for (int mt = 0; mt < 2; mt++) {
                uint32_t off = (uint32_t)(a_row + mt * 16) * 128 + (k * 2 + a_sh) * 16;
                uint32_t sw = off ^ ((off >> 3) & 0x70);
                ldsm_x4(afr[mt], Ab + sw);
            }
            uint32_t bfr[4][2];
            #pragma unroll
            for (int nt = 0; nt < 4; nt++) {
                uint32_t off = (uint32_t)(b_row + nt * 8) * 128 + (k * 2 + b_sh) * 16;
                uint32_t sw = off ^ ((off >> 3) & 0x70);
                ldsm_x2(bfr[nt], Bb + sw);
            }
            #pragma unroll
            for (int mt = 0; mt < 2; mt++)
                #pragma unroll
                for (int nt = 0; nt < 4; nt++)
                    mma_bf16(sim[mt][nt], afr[mt], bfr[nt]);
        }

        // sigma(x) = 0.5 + 0.5*tanh(x/2); accumulate 0.5*tanh(x/2)
        #pragma unroll
        for (int mt = 0; mt < 2; mt++)
            #pragma unroll
            for (int nt = 0; nt < 4; nt++)
                #pragma unroll
                for (int r = 0; r < 4; r++) {
                    float t = tanh_fast(sim[mt][nt][r] * 0.5f);
                    acc[mt][nt][r] = fmaf(0.5f, t, acc[mt][nt][r]);
                }

        __syncthreads();
    }

    // epilogue: mean = acc/8 + 0.5
    const int g = lane >> 2;
    const int tig = lane & 3;
    #pragma unroll
    for (int mt = 0; mt < 2; mt++) {
        int gn0 = n0 + wm * 32 + mt * 16 + g;
        #pragma unroll
        for (int nt = 0; nt < 4; nt++) {
            int gm = m0 + wn * 32 + nt * 8 + tig * 2;
            if (gm < NNc) {
                if (gn0 < NNc) {
                    float2 v = make_float2(fmaf(acc[mt][nt][0], 0.125f, 0.5f),
                                           fmaf(acc[mt][nt][1], 0.125f, 0.5f));
                    *(float2*)&adj[(size_t)gn0 * NNc + gm] = v;
                }
                if (gn0 + 8 < NNc) {
                    float2 v = make_float2(fmaf(acc[mt][nt][2], 0.125f, 0.5f),
                                           fmaf(acc[mt][nt][3], 0.125f, 0.5f));
                    *(float2*)&adj[(size_t)(gn0 + 8) * NNc + gm] = v;
                }
            }
        }
    }
}

// =====================================================================
// launch: fork-join across 3 streams
// =====================================================================
extern "C" void kernel_launch(void* const* d_in, const int* in_sizes, int n_in,
                              void* d_out, int out_size) {
    (void)in_sizes; (void)n_in; (void)out_size;
    const float* lm_X     = (const float*)d_in[0];
    const float* lm_Y     = (const float*)d_in[1];
    const float* tg_X     = (const float*)d_in[2];
    const float* lm_delay = (const float*)d_in[4];
    const float* tg_delay = (const float*)d_in[5];
    const float* W_emb    = (const float*)d_in[6];
    const float* b_emb    = (const float*)d_in[7];
    const float* w1       = (const float*)d_in[8];
    const float* w2       = (const float*)d_in[9];

    float* out     = (float*)d_out;
    float* y_pred  = out;                       // [2000, 2]
    float* adj     = out + 4000;                // [4000, 4000]
    float* teacher = adj + (size_t)NNc * NNc;   // [4000, 4000]

    static bool init = false;
    static cudaStream_t s1, s2;
    static cudaEvent_t ef, e_fill, e_join;
    const int ADJ_SMEM = 2 * STAGE_BYTES + 1024;  // 66560
    if (!init) {
        cudaFuncSetAttribute(adj_mm_kernel,
                             cudaFuncAttributeMaxDynamicSharedMemorySize, ADJ_SMEM);
        cudaStreamCreateWithFlags(&s1, cudaStreamNonBlocking);
        cudaStreamCreateWithFlags(&s2, cudaStreamNonBlocking);
        cudaEventCreateWithFlags(&ef,     cudaEventDisableTiming);
        cudaEventCreateWithFlags(&e_fill, cudaEventDisableTiming);
        cudaEventCreateWithFlags(&e_join, cudaEventDisableTiming);
        init = true;
    }

    // fork
    cudaEventRecord(ef, 0);
    cudaStreamWaitEvent(s1, ef, 0);
    cudaStreamWaitEvent(s2, ef, 0);

    // branch s1: teacher base fill
    fill_teacher_kernel<<<dim3(4, NNc), 256, 0, s1>>>(teacher);
    cudaEventRecord(e_fill, s1);

    // branch s2: knn pipeline
    sq_kernel<<<8, 256, 0, s2>>>(lm_X);
    xt_kernel<<<(Ec * MPADc + 255) / 256, 256, 0, s2>>>(lm_X);
    d2_kernel<<<528, 256, 0, s2>>>();
    cudaStreamWaitEvent(s2, e_fill, 0);
    topk_kernel<<<N1c, 256, 0, s2>>>(lm_Y, y_pred, teacher);
    cudaEventRecord(e_join, s2);

    // main branch: embedding -> big adjacency GEMM
    embed_kernel<<<512, 256>>>(lm_X, tg_X, lm_delay, tg_delay,
                               W_emb, b_emb, w1, w2);
    adj_mm_kernel<<<dim3(32, 32), 512, ADJ_SMEM>>>(adj);

    // join
    cudaStreamWaitEvent(0, e_join, 0);
}